// round 1
// baseline (speedup 1.0000x reference)
#include <cuda_runtime.h>

#define SEQ   2048
#define BATCH 2
#define NTOK  (SEQ * BATCH)      // 4096
#define DIMM  2048
#define NH    32
#define NKV   8
#define HD    64
#define KVC   (2 * NKV * HD)     // 1024: cols [0,512)=K, [512,1024)=V

// ---- scratch (static device globals: allocation-free) ----
__device__ float g_q[(size_t)NTOK * DIMM];   // Q after proj (+RoPE)
__device__ float g_kv[(size_t)NTOK * KVC];   // KV after proj (K gets RoPE in place)
__device__ float g_att[(size_t)NTOK * DIMM]; // attention output (b, n, h*64+d)

// ============================================================================
// SGEMM: C(M,N) = A(M,K) @ B(K,N), all row-major fp32.
// 128x128 tile, BK=8, 256 threads, 8x8 per-thread microtile.
// Requires M%128==0, N%128==0, K%8==0 (true for all three calls).
// ============================================================================
__global__ __launch_bounds__(256) void sgemm128(
    const float* __restrict__ A, const float* __restrict__ B,
    float* __restrict__ C, int M, int N, int K)
{
    __shared__ float As[8][128];   // transposed A tile
    __shared__ float Bs[8][128];

    const int tid = threadIdx.x;
    const int tr  = tid >> 4;          // 0..15
    const int tc  = tid & 15;          // 0..15

    const int arow = tid >> 1;             // 0..127
    const int avec = (tid & 1) * 4;        // 0 or 4
    const int bkr  = tid >> 5;             // 0..7
    const int bcv  = (tid & 31) * 4;       // 0..124

    const float* Aptr = A + (size_t)(blockIdx.y * 128 + arow) * K + avec;
    const float* Bptr = B + (size_t)bkr * N + blockIdx.x * 128 + bcv;

    float acc[8][8] = {};

    for (int k0 = 0; k0 < K; k0 += 8) {
        float4 a = *(const float4*)(Aptr + k0);
        As[avec + 0][arow] = a.x;
        As[avec + 1][arow] = a.y;
        As[avec + 2][arow] = a.z;
        As[avec + 3][arow] = a.w;
        float4 b4 = *(const float4*)(Bptr + (size_t)k0 * N);
        *(float4*)&Bs[bkr][bcv] = b4;
        __syncthreads();

        #pragma unroll
        for (int k = 0; k < 8; ++k) {
            float rm[8], rn[8];
            *(float4*)&rm[0] = *(const float4*)&As[k][tr * 8];
            *(float4*)&rm[4] = *(const float4*)&As[k][tr * 8 + 4];
            *(float4*)&rn[0] = *(const float4*)&Bs[k][tc * 8];
            *(float4*)&rn[4] = *(const float4*)&Bs[k][tc * 8 + 4];
            #pragma unroll
            for (int i = 0; i < 8; ++i)
                #pragma unroll
                for (int j = 0; j < 8; ++j)
                    acc[i][j] += rm[i] * rn[j];
        }
        __syncthreads();
    }

    float* Cb = C + (size_t)(blockIdx.y * 128 + tr * 8) * N + blockIdx.x * 128 + tc * 8;
    #pragma unroll
    for (int i = 0; i < 8; ++i) {
        *(float4*)(Cb + (size_t)i * N)     = make_float4(acc[i][0], acc[i][1], acc[i][2], acc[i][3]);
        *(float4*)(Cb + (size_t)i * N + 4) = make_float4(acc[i][4], acc[i][5], acc[i][6], acc[i][7]);
    }
}

// ============================================================================
// RoPE: interleaved pairs (2i, 2i+1), 32 freqs, position = token index in seq.
// Applies to Q (all 32 heads) and K half of KV (8 heads, cols [0,512)).
// ============================================================================
__global__ void rope_kernel(float* __restrict__ qb, float* __restrict__ kvb,
                            const float* __restrict__ cb, const float* __restrict__ sb)
{
    const int QP = NTOK * (DIMM / 2);          // 4194304 q pairs
    const int KP = NTOK * ((NKV * HD) / 2);    // 1048576 k pairs
    int idx = blockIdx.x * blockDim.x + threadIdx.x;
    if (idx < QP) {
        int row = idx >> 10;         // / 1024 pairs per row
        int pc  = idx & 1023;
        int i   = pc & 31;           // freq index
        int n   = row & (SEQ - 1);
        float c = cb[n * 32 + i], s = sb[n * 32 + i];
        float* p = qb + (size_t)row * DIMM + (pc >> 5) * HD + 2 * i;
        float xe = p[0], xo = p[1];
        p[0] = xe * c - xo * s;
        p[1] = xe * s + xo * c;
    } else if (idx < QP + KP) {
        int t   = idx - QP;
        int row = t >> 8;            // / 256 pairs per row
        int pc  = t & 255;
        int i   = pc & 31;
        int n   = row & (SEQ - 1);
        float c = cb[n * 32 + i], s = sb[n * 32 + i];
        float* p = kvb + (size_t)row * KVC + (pc >> 5) * HD + 2 * i;
        float xe = p[0], xo = p[1];
        p[0] = xe * c - xo * s;
        p[1] = xe * s + xo * c;
    }
}

// ============================================================================
// Causal flash attention, GQA (q head h -> kv head h % 8, per jnp.tile).
// CTA: 64 queries x one (b,h); key tiles of 64; online softmax.
// 256 threads: 16x16 grid, 4x4 microtiles for both QK^T and PV.
// Dynamic smem: Q,K,V,S tiles 64x64 + m/l/corr rows.
// ============================================================================
#define FL_SMEM ((4 * 64 * 64 + 3 * 64) * 4)

__global__ __launch_bounds__(256) void flash_kernel(
    const float* __restrict__ q, const float* __restrict__ kv,
    float* __restrict__ o)
{
    extern __shared__ float sm[];
    float* Qs   = sm;
    float* Ks   = sm + 4096;
    float* Vs   = sm + 8192;
    float* Ss   = sm + 12288;
    float* mrow = sm + 16384;
    float* lrow = mrow + 64;
    float* crow = lrow + 64;

    const int qt = blockIdx.x, h = blockIdx.y, b = blockIdx.z;
    const int kvh = h & (NKV - 1);
    const int tid = threadIdx.x;
    const int tr = tid >> 4, tc = tid & 15;
    const int lr  = tid >> 2;          // 0..63 (loader/softmax row)
    const int lcv = (tid & 3) * 16;    // 16-col segment

    // load Q tile, pre-scaled by 1/sqrt(64)
    {
        const float* src = q + (size_t)(b * SEQ + qt * 64 + lr) * DIMM + h * HD + lcv;
        float* dst = Qs + lr * 64 + lcv;
        #pragma unroll
        for (int v = 0; v < 16; v += 4) {
            float4 t = *(const float4*)(src + v);
            t.x *= 0.125f; t.y *= 0.125f; t.z *= 0.125f; t.w *= 0.125f;
            *(float4*)(dst + v) = t;
        }
    }
    if (tid < 64) { mrow[tid] = -1e30f; lrow[tid] = 0.f; }

    float acc[4][4] = {};

    for (int kt = 0; kt <= qt; ++kt) {
        // load K, V tiles
        {
            const float* ksrc = kv + (size_t)(b * SEQ + kt * 64 + lr) * KVC + kvh * HD + lcv;
            float* kdst = Ks + lr * 64 + lcv;
            float* vdst = Vs + lr * 64 + lcv;
            #pragma unroll
            for (int v = 0; v < 16; v += 4) {
                *(float4*)(kdst + v) = *(const float4*)(ksrc + v);
                *(float4*)(vdst + v) = *(const float4*)(ksrc + 512 + v);
            }
        }
        __syncthreads();   // Q (first iter) + K/V visible

        // S = Q @ K^T (4x4 microtile)
        float s[4][4] = {};
        #pragma unroll 4
        for (int d = 0; d < 64; d += 4) {
            float rq[4][4], rk[4][4];
            #pragma unroll
            for (int i = 0; i < 4; ++i)
                *(float4*)&rq[i][0] = *(const float4*)&Qs[(tr * 4 + i) * 64 + d];
            #pragma unroll
            for (int j = 0; j < 4; ++j)
                *(float4*)&rk[j][0] = *(const float4*)&Ks[(tc * 4 + j) * 64 + d];
            #pragma unroll
            for (int i = 0; i < 4; ++i)
                #pragma unroll
                for (int j = 0; j < 4; ++j)
                    s[i][j] += rq[i][0] * rk[j][0] + rq[i][1] * rk[j][1]
                             + rq[i][2] * rk[j][2] + rq[i][3] * rk[j][3];
        }
        if (kt == qt) {   // diagonal tile: causal mask
            #pragma unroll
            for (int i = 0; i < 4; ++i)
                #pragma unroll
                for (int j = 0; j < 4; ++j)
                    if (tc * 4 + j > tr * 4 + i) s[i][j] = -1e30f;
        }
        #pragma unroll
        for (int i = 0; i < 4; ++i)
            *(float4*)&Ss[(tr * 4 + i) * 64 + tc * 4] =
                make_float4(s[i][0], s[i][1], s[i][2], s[i][3]);
        __syncthreads();

        // online softmax: 4 lanes per row (same warp, contiguous)
        {
            float* Sr = Ss + lr * 64 + lcv;
            float mx = -1e30f;
            #pragma unroll
            for (int c2 = 0; c2 < 16; ++c2) mx = fmaxf(mx, Sr[c2]);
            mx = fmaxf(mx, __shfl_xor_sync(0xffffffffu, mx, 1));
            mx = fmaxf(mx, __shfl_xor_sync(0xffffffffu, mx, 2));
            float mold = mrow[lr];
            float mnew = fmaxf(mold, mx);
            float corr = __expf(mold - mnew);   // 0 on first tile (underflow)
            float sum = 0.f;
            #pragma unroll
            for (int c2 = 0; c2 < 16; ++c2) {
                float p = __expf(Sr[c2] - mnew);
                Sr[c2] = p;
                sum += p;
            }
            sum += __shfl_xor_sync(0xffffffffu, sum, 1);
            sum += __shfl_xor_sync(0xffffffffu, sum, 2);
            if ((tid & 3) == 0) {
                mrow[lr] = mnew;
                lrow[lr] = lrow[lr] * corr + sum;
                crow[lr] = corr;
            }
        }
        __syncthreads();

        // O = O*corr + P @ V (4x4 microtile)
        {
            #pragma unroll
            for (int i = 0; i < 4; ++i) {
                float cf = crow[tr * 4 + i];
                #pragma unroll
                for (int j = 0; j < 4; ++j) acc[i][j] *= cf;
            }
            #pragma unroll 4
            for (int kk = 0; kk < 64; kk += 4) {
                float rp[4][4];
                #pragma unroll
                for (int i = 0; i < 4; ++i)
                    *(float4*)&rp[i][0] = *(const float4*)&Ss[(tr * 4 + i) * 64 + kk];
                #pragma unroll
                for (int t2 = 0; t2 < 4; ++t2) {
                    float4 rv = *(const float4*)&Vs[(kk + t2) * 64 + tc * 4];
                    #pragma unroll
                    for (int i = 0; i < 4; ++i) {
                        float p = rp[i][t2];
                        acc[i][0] += p * rv.x;
                        acc[i][1] += p * rv.y;
                        acc[i][2] += p * rv.z;
                        acc[i][3] += p * rv.w;
                    }
                }
            }
        }
        __syncthreads();   // protect Ks/Vs/Ss before next tile
    }

    // epilogue: normalize, write to (b, n, h*64+d) layout
    float li[4];
    #pragma unroll
    for (int i = 0; i < 4; ++i) li[i] = 1.f / lrow[tr * 4 + i];
    float* ob = o + (size_t)(b * SEQ + qt * 64) * DIMM + h * HD;
    #pragma unroll
    for (int i = 0; i < 4; ++i) {
        *(float4*)(ob + (size_t)(tr * 4 + i) * DIMM + tc * 4) =
            make_float4(acc[i][0] * li[i], acc[i][1] * li[i],
                        acc[i][2] * li[i], acc[i][3] * li[i]);
    }
}

// ============================================================================
extern "C" void kernel_launch(void* const* d_in, const int* in_sizes, int n_in,
                              void* d_out, int out_size)
{
    const float* x   = (const float*)d_in[0];
    const float* Wq  = (const float*)d_in[1];
    const float* Wkv = (const float*)d_in[2];
    const float* Wo  = (const float*)d_in[3];
    const float* cb  = (const float*)d_in[4];
    const float* sb  = (const float*)d_in[5];
    // d_in[6] = mask (implemented as causal), d_in[7] = start_pos (== 0)
    float* out = (float*)d_out;

    float *qb, *kvb, *ab;
    cudaGetSymbolAddress((void**)&qb,  g_q);
    cudaGetSymbolAddress((void**)&kvb, g_kv);
    cudaGetSymbolAddress((void**)&ab,  g_att);

    cudaFuncSetAttribute(flash_kernel,
                         cudaFuncAttributeMaxDynamicSharedMemorySize, FL_SMEM);

    // Q = x @ Wq   (4096 x 2048 x 2048)
    sgemm128<<<dim3(DIMM / 128, NTOK / 128), 256>>>(x, Wq, qb, NTOK, DIMM, DIMM);
    // KV = x @ Wkv (4096 x 1024 x 2048)
    sgemm128<<<dim3(KVC / 128, NTOK / 128), 256>>>(x, Wkv, kvb, NTOK, KVC, DIMM);
    // RoPE on Q and K
    {
        int totalPairs = NTOK * (DIMM / 2) + NTOK * ((NKV * HD) / 2);
        rope_kernel<<<(totalPairs + 255) / 256, 256>>>(qb, kvb, cb, sb);
    }
    // causal GQA flash attention
    flash_kernel<<<dim3(SEQ / 64, NH, BATCH), 256, FL_SMEM>>>(qb, kvb, ab);
    // out = att @ Wo (4096 x 2048 x 2048)
    sgemm128<<<dim3(DIMM / 128, NTOK / 128), 256>>>(ab, Wo, out, NTOK, DIMM, DIMM);
}

// round 3
// speedup vs baseline: 1.4156x; 1.4156x over previous
#include <cuda_runtime.h>
#include <cstdint>

#define SEQ   2048
#define BATCH 2
#define NTOK  (SEQ * BATCH)      // 4096
#define DIMM  2048
#define NH    32
#define NKV   8
#define HD    64
#define KVC   (2 * NKV * HD)     // 1024: cols [0,512)=K, [512,1024)=V

// ---- scratch (static device globals: allocation-free) ----
__device__ float g_q[(size_t)NTOK * DIMM];    // Q after proj (+RoPE)
__device__ float g_kv[(size_t)NTOK * KVC];    // KV after proj (K gets RoPE in place)
__device__ float g_att[(size_t)NTOK * DIMM];  // attention output (b, n, h*64+d)
__device__ float g_wqt[(size_t)DIMM * DIMM];  // Wq^T  [N][K]
__device__ float g_wkvt[(size_t)KVC * DIMM];  // Wkv^T [N][K]
__device__ float g_wot[(size_t)DIMM * DIMM];  // Wo^T  [N][K]

__device__ __forceinline__ float to_tf32(float x) {
    float y;
    asm("cvt.rna.tf32.f32 %0, %1;" : "=f"(y) : "f"(x));
    return y;
}
__device__ __forceinline__ void mma_tf32(float* d, const uint32_t* a, const uint32_t* b) {
    asm volatile(
        "mma.sync.aligned.m16n8k8.row.col.f32.tf32.tf32.f32 "
        "{%0,%1,%2,%3}, {%4,%5,%6,%7}, {%8,%9}, {%0,%1,%2,%3};"
        : "+f"(d[0]), "+f"(d[1]), "+f"(d[2]), "+f"(d[3])
        : "r"(a[0]), "r"(a[1]), "r"(a[2]), "r"(a[3]), "r"(b[0]), "r"(b[1]));
}

// ============================================================================
// Weight transpose: out[c][r] = in[r][c].  in: R x C (row-major).
// ============================================================================
__global__ void transpose32(const float* __restrict__ in, float* __restrict__ out,
                            int R, int C)
{
    __shared__ float t[32][33];
    const int bc = blockIdx.x * 32, br = blockIdx.y * 32;
    const int tx = threadIdx.x;
    for (int i = threadIdx.y; i < 32; i += 8)
        t[i][tx] = in[(size_t)(br + i) * C + bc + tx];
    __syncthreads();
    for (int i = threadIdx.y; i < 32; i += 8)
        out[(size_t)(bc + i) * R + br + tx] = t[tx][i];
}

// ============================================================================
// tf32 mma.sync GEMM:  C(M,N) = A(M,K) @ Bt(N,K)^T    (A, Bt row-major K-major)
// CTA tile 128x128, BK=32, 256 threads (8 warps, 4M x 2N), warp tile 32x64.
// m16n8k8 fragments, fp32 accumulate.  SMEM padded rows (36 floats) ->
// conflict-free fragment loads.  Ping-pong buffers, register-staged prefetch.
// ============================================================================
#define BK      32
#define GPAD    36                       // floats per padded smem row
#define TILE_F  (128 * GPAD)             // floats per operand per stage
#define G_SMEM  (4 * TILE_F * 4)         // bytes: A0,A1,B0,B1

__global__ __launch_bounds__(256) void gemm_mma(
    const float* __restrict__ A, const float* __restrict__ Bt,
    float* __restrict__ C, int M, int N, int K)
{
    extern __shared__ float sm[];
    float* As = sm;                  // [2][128][GPAD]
    float* Bs = sm + 2 * TILE_F;     // [2][128][GPAD]

    const int tid = threadIdx.x;
    const int wid = tid >> 5, lane = tid & 31;
    const int g   = lane >> 2;       // groupID 0..7
    const int tg  = lane & 3;        // threadInGroup 0..3
    const int wm  = wid & 3;         // warp M block (32 rows)
    const int wn  = wid >> 2;        // warp N block (64 cols)
    const int m0  = blockIdx.y * 128, n0 = blockIdx.x * 128;

    const float* Ab = A  + (size_t)m0 * K;
    const float* Bb = Bt + (size_t)n0 * K;

    // loader mapping: v = tid + 256*i -> row v>>3, float4 (v&7)
    const int lrow[4] = { tid >> 3, (tid + 256) >> 3, (tid + 512) >> 3, (tid + 768) >> 3 };
    const int lcol    = (tid & 7) * 4;

    float acc[2][8][4];
    #pragma unroll
    for (int mt = 0; mt < 2; ++mt)
        #pragma unroll
        for (int nt = 0; nt < 8; ++nt)
            #pragma unroll
            for (int v = 0; v < 4; ++v) acc[mt][nt][v] = 0.f;

    const int NC = K / BK;
    float4 ra[4], rb[4];

    // prologue: global->regs chunk 0, cvt+store stage 0
    #pragma unroll
    for (int i = 0; i < 4; ++i) {
        ra[i] = *(const float4*)(Ab + (size_t)lrow[i] * K + lcol);
        rb[i] = *(const float4*)(Bb + (size_t)lrow[i] * K + lcol);
    }
    #pragma unroll
    for (int i = 0; i < 4; ++i) {
        float* pa = As + lrow[i] * GPAD + lcol;
        pa[0] = to_tf32(ra[i].x); pa[1] = to_tf32(ra[i].y);
        pa[2] = to_tf32(ra[i].z); pa[3] = to_tf32(ra[i].w);
        float* pb = Bs + lrow[i] * GPAD + lcol;
        pb[0] = to_tf32(rb[i].x); pb[1] = to_tf32(rb[i].y);
        pb[2] = to_tf32(rb[i].z); pb[3] = to_tf32(rb[i].w);
    }
    __syncthreads();

    for (int c = 0; c < NC; ++c) {
        const int s = c & 1;
        // prefetch next chunk into registers
        if (c + 1 < NC) {
            const int k0 = (c + 1) * BK;
            #pragma unroll
            for (int i = 0; i < 4; ++i) {
                ra[i] = *(const float4*)(Ab + (size_t)lrow[i] * K + k0 + lcol);
                rb[i] = *(const float4*)(Bb + (size_t)lrow[i] * K + k0 + lcol);
            }
        }
        // compute on stage s
        const float* Ac = As + s * TILE_F;
        const float* Bc = Bs + s * TILE_F;
        #pragma unroll
        for (int ks = 0; ks < 4; ++ks) {
            const int k0 = ks * 8;
            uint32_t af[2][4], bf[8][2];
            #pragma unroll
            for (int mt = 0; mt < 2; ++mt) {
                const float* p = Ac + (wm * 32 + mt * 16 + g) * GPAD + k0 + tg;
                af[mt][0] = __float_as_uint(p[0]);
                af[mt][1] = __float_as_uint(p[8 * GPAD]);
                af[mt][2] = __float_as_uint(p[4]);
                af[mt][3] = __float_as_uint(p[8 * GPAD + 4]);
            }
            #pragma unroll
            for (int nt = 0; nt < 8; ++nt) {
                const float* p = Bc + (wn * 64 + nt * 8 + g) * GPAD + k0 + tg;
                bf[nt][0] = __float_as_uint(p[0]);
                bf[nt][1] = __float_as_uint(p[4]);
            }
            #pragma unroll
            for (int mt = 0; mt < 2; ++mt)
                #pragma unroll
                for (int nt = 0; nt < 8; ++nt)
                    mma_tf32(acc[mt][nt], af[mt], bf[nt]);
        }
        // store next chunk into other stage (its last readers synced already)
        if (c + 1 < NC) {
            float* An = As + (s ^ 1) * TILE_F;
            float* Bn = Bs + (s ^ 1) * TILE_F;
            #pragma unroll
            for (int i = 0; i < 4; ++i) {
                float* pa = An + lrow[i] * GPAD + lcol;
                pa[0] = to_tf32(ra[i].x); pa[1] = to_tf32(ra[i].y);
                pa[2] = to_tf32(ra[i].z); pa[3] = to_tf32(ra[i].w);
                float* pb = Bn + lrow[i] * GPAD + lcol;
                pb[0] = to_tf32(rb[i].x); pb[1] = to_tf32(rb[i].y);
                pb[2] = to_tf32(rb[i].z); pb[3] = to_tf32(rb[i].w);
            }
            __syncthreads();
        }
    }

    // epilogue
    #pragma unroll
    for (int mt = 0; mt < 2; ++mt) {
        const int row = m0 + wm * 32 + mt * 16 + g;
        #pragma unroll
        for (int nt = 0; nt < 8; ++nt) {
            const int col = n0 + wn * 64 + nt * 8 + 2 * tg;
            *(float2*)(C + (size_t)row * N + col) =
                make_float2(acc[mt][nt][0], acc[mt][nt][1]);
            *(float2*)(C + (size_t)(row + 8) * N + col) =
                make_float2(acc[mt][nt][2], acc[mt][nt][3]);
        }
    }
}

// ============================================================================
// RoPE: interleaved pairs (2i, 2i+1), 32 freqs, position = token index in seq.
// ============================================================================
__global__ void rope_kernel(float* __restrict__ qb, float* __restrict__ kvb,
                            const float* __restrict__ cb, const float* __restrict__ sb)
{
    const int QP = NTOK * (DIMM / 2);
    const int KP = NTOK * ((NKV * HD) / 2);
    int idx = blockIdx.x * blockDim.x + threadIdx.x;
    if (idx < QP) {
        int row = idx >> 10;
        int pc  = idx & 1023;
        int i   = pc & 31;
        int n   = row & (SEQ - 1);
        float c = cb[n * 32 + i], s = sb[n * 32 + i];
        float* p = qb + (size_t)row * DIMM + (pc >> 5) * HD + 2 * i;
        float xe = p[0], xo = p[1];
        p[0] = xe * c - xo * s;
        p[1] = xe * s + xo * c;
    } else if (idx < QP + KP) {
        int t   = idx - QP;
        int row = t >> 8;
        int pc  = t & 255;
        int i   = pc & 31;
        int n   = row & (SEQ - 1);
        float c = cb[n * 32 + i], s = sb[n * 32 + i];
        float* p = kvb + (size_t)row * KVC + (pc >> 5) * HD + 2 * i;
        float xe = p[0], xo = p[1];
        p[0] = xe * c - xo * s;
        p[1] = xe * s + xo * c;
    }
}

// ============================================================================
// Causal flash attention, GQA (q head h -> kv head h % 8).  Unchanged (passing).
// ============================================================================
#define FL_SMEM ((4 * 64 * 64 + 3 * 64) * 4)

__global__ __launch_bounds__(256) void flash_kernel(
    const float* __restrict__ q, const float* __restrict__ kv,
    float* __restrict__ o)
{
    extern __shared__ float fsm[];
    float* Qs   = fsm;
    float* Ks   = fsm + 4096;
    float* Vs   = fsm + 8192;
    float* Ss   = fsm + 12288;
    float* mrow = fsm + 16384;
    float* lrow = mrow + 64;
    float* crow = lrow + 64;

    const int qt = blockIdx.x, h = blockIdx.y, b = blockIdx.z;
    const int kvh = h & (NKV - 1);
    const int tid = threadIdx.x;
    const int tr = tid >> 4, tc = tid & 15;
    const int lr  = tid >> 2;
    const int lcv = (tid & 3) * 16;

    {
        const float* src = q + (size_t)(b * SEQ + qt * 64 + lr) * DIMM + h * HD + lcv;
        float* dst = Qs + lr * 64 + lcv;
        #pragma unroll
        for (int v = 0; v < 16; v += 4) {
            float4 t = *(const float4*)(src + v);
            t.x *= 0.125f; t.y *= 0.125f; t.z *= 0.125f; t.w *= 0.125f;
            *(float4*)(dst + v) = t;
        }
    }
    if (tid < 64) { mrow[tid] = -1e30f; lrow[tid] = 0.f; }

    float acc[4][4] = {};

    for (int kt = 0; kt <= qt; ++kt) {
        {
            const float* ksrc = kv + (size_t)(b * SEQ + kt * 64 + lr) * KVC + kvh * HD + lcv;
            float* kdst = Ks + lr * 64 + lcv;
            float* vdst = Vs + lr * 64 + lcv;
            #pragma unroll
            for (int v = 0; v < 16; v += 4) {
                *(float4*)(kdst + v) = *(const float4*)(ksrc + v);
                *(float4*)(vdst + v) = *(const float4*)(ksrc + 512 + v);
            }
        }
        __syncthreads();

        float s[4][4] = {};
        #pragma unroll 4
        for (int d = 0; d < 64; d += 4) {
            float rq[4][4], rk[4][4];
            #pragma unroll
            for (int i = 0; i < 4; ++i)
                *(float4*)&rq[i][0] = *(const float4*)&Qs[(tr * 4 + i) * 64 + d];
            #pragma unroll
            for (int j = 0; j < 4; ++j)
                *(float4*)&rk[j][0] = *(const float4*)&Ks[(tc * 4 + j) * 64 + d];
            #pragma unroll
            for (int i = 0; i < 4; ++i)
                #pragma unroll
                for (int j = 0; j < 4; ++j)
                    s[i][j] += rq[i][0] * rk[j][0] + rq[i][1] * rk[j][1]
                             + rq[i][2] * rk[j][2] + rq[i][3] * rk[j][3];
        }
        if (kt == qt) {
            #pragma unroll
            for (int i = 0; i < 4; ++i)
                #pragma unroll
                for (int j = 0; j < 4; ++j)
                    if (tc * 4 + j > tr * 4 + i) s[i][j] = -1e30f;
        }
        #pragma unroll
        for (int i = 0; i < 4; ++i)
            *(float4*)&Ss[(tr * 4 + i) * 64 + tc * 4] =
                make_float4(s[i][0], s[i][1], s[i][2], s[i][3]);
        __syncthreads();

        {
            float* Sr = Ss + lr * 64 + lcv;
            float mx = -1e30f;
            #pragma unroll
            for (int c2 = 0; c2 < 16; ++c2) mx = fmaxf(mx, Sr[c2]);
            mx = fmaxf(mx, __shfl_xor_sync(0xffffffffu, mx, 1));
            mx = fmaxf(mx, __shfl_xor_sync(0xffffffffu, mx, 2));
            float mold = mrow[lr];
            float mnew = fmaxf(mold, mx);
            float corr = __expf(mold - mnew);
            float sum = 0.f;
            #pragma unroll
            for (int c2 = 0; c2 < 16; ++c2) {
                float p = __expf(Sr[c2] - mnew);
                Sr[c2] = p;
                sum += p;
            }
            sum += __shfl_xor_sync(0xffffffffu, sum, 1);
            sum += __shfl_xor_sync(0xffffffffu, sum, 2);
            if ((tid & 3) == 0) {
                mrow[lr] = mnew;
                lrow[lr] = lrow[lr] * corr + sum;
                crow[lr] = corr;
            }
        }
        __syncthreads();

        {
            #pragma unroll
            for (int i = 0; i < 4; ++i) {
                float cf = crow[tr * 4 + i];
                #pragma unroll
                for (int j = 0; j < 4; ++j) acc[i][j] *= cf;
            }
            #pragma unroll 4
            for (int kk = 0; kk < 64; kk += 4) {
                float rp[4][4];
                #pragma unroll
                for (int i = 0; i < 4; ++i)
                    *(float4*)&rp[i][0] = *(const float4*)&Ss[(tr * 4 + i) * 64 + kk];
                #pragma unroll
                for (int t2 = 0; t2 < 4; ++t2) {
                    float4 rv = *(const float4*)&Vs[(kk + t2) * 64 + tc * 4];
                    #pragma unroll
                    for (int i = 0; i < 4; ++i) {
                        float p = rp[i][t2];
                        acc[i][0] += p * rv.x;
                        acc[i][1] += p * rv.y;
                        acc[i][2] += p * rv.z;
                        acc[i][3] += p * rv.w;
                    }
                }
            }
        }
        __syncthreads();
    }

    float li[4];
    #pragma unroll
    for (int i = 0; i < 4; ++i) li[i] = 1.f / lrow[tr * 4 + i];
    float* ob = o + (size_t)(b * SEQ + qt * 64) * DIMM + h * HD;
    #pragma unroll
    for (int i = 0; i < 4; ++i) {
        *(float4*)(ob + (size_t)(tr * 4 + i) * DIMM + tc * 4) =
            make_float4(acc[i][0] * li[i], acc[i][1] * li[i],
                        acc[i][2] * li[i], acc[i][3] * li[i]);
    }
}

// ============================================================================
extern "C" void kernel_launch(void* const* d_in, const int* in_sizes, int n_in,
                              void* d_out, int out_size)
{
    const float* x   = (const float*)d_in[0];
    const float* Wq  = (const float*)d_in[1];
    const float* Wkv = (const float*)d_in[2];
    const float* Wo  = (const float*)d_in[3];
    const float* cb  = (const float*)d_in[4];
    const float* sb  = (const float*)d_in[5];
    float* out = (float*)d_out;

    float *qb, *kvb, *ab, *wqt, *wkvt, *wot;
    cudaGetSymbolAddress((void**)&qb,   g_q);
    cudaGetSymbolAddress((void**)&kvb,  g_kv);
    cudaGetSymbolAddress((void**)&ab,   g_att);
    cudaGetSymbolAddress((void**)&wqt,  g_wqt);
    cudaGetSymbolAddress((void**)&wkvt, g_wkvt);
    cudaGetSymbolAddress((void**)&wot,  g_wot);

    cudaFuncSetAttribute(flash_kernel,
                         cudaFuncAttributeMaxDynamicSharedMemorySize, FL_SMEM);
    cudaFuncSetAttribute(gemm_mma,
                         cudaFuncAttributeMaxDynamicSharedMemorySize, G_SMEM);

    // transpose weights to [N][K]
    transpose32<<<dim3(DIMM / 32, DIMM / 32), dim3(32, 8)>>>(Wq, wqt, DIMM, DIMM);
    transpose32<<<dim3(KVC / 32, DIMM / 32), dim3(32, 8)>>>(Wkv, wkvt, DIMM, KVC);
    transpose32<<<dim3(DIMM / 32, DIMM / 32), dim3(32, 8)>>>(Wo, wot, DIMM, DIMM);

    // Q = x @ Wq   (4096 x 2048 x 2048)
    gemm_mma<<<dim3(DIMM / 128, NTOK / 128), 256, G_SMEM>>>(x, wqt, qb, NTOK, DIMM, DIMM);
    // KV = x @ Wkv (4096 x 1024 x 2048)
    gemm_mma<<<dim3(KVC / 128, NTOK / 128), 256, G_SMEM>>>(x, wkvt, kvb, NTOK, KVC, DIMM);
    // RoPE on Q and K
    {
        int totalPairs = NTOK * (DIMM / 2) + NTOK * ((NKV * HD) / 2);
        rope_kernel<<<(totalPairs + 255) / 256, 256>>>(qb, kvb, cb, sb);
    }
    // causal GQA flash attention
    flash_kernel<<<dim3(SEQ / 64, NH, BATCH), 256, FL_SMEM>>>(qb, kvb, ab);
    // out = att @ Wo (4096 x 2048 x 2048)
    gemm_mma<<<dim3(DIMM / 128, NTOK / 128), 256, G_SMEM>>>(ab, wot, out, NTOK, DIMM, DIMM);
}

// round 4
// speedup vs baseline: 4.8383x; 3.4177x over previous
#include <cuda_runtime.h>
#include <cstdint>

#define SEQ   2048
#define BATCH 2
#define NTOK  (SEQ * BATCH)      // 4096
#define DIMM  2048
#define NH    32
#define NKV   8
#define HD    64
#define KVC   (2 * NKV * HD)     // 1024: cols [0,512)=K, [512,1024)=V

// ---- scratch (static device globals: allocation-free) ----
__device__ float g_q[(size_t)NTOK * DIMM];
__device__ float g_kv[(size_t)NTOK * KVC];
__device__ float g_att[(size_t)NTOK * DIMM];
__device__ float g_wqt[(size_t)DIMM * DIMM];
__device__ float g_wkvt[(size_t)KVC * DIMM];
__device__ float g_wot[(size_t)DIMM * DIMM];

__device__ __forceinline__ float to_tf32(float x) {
    float y;
    asm("cvt.rna.tf32.f32 %0, %1;" : "=f"(y) : "f"(x));
    return y;
}
__device__ __forceinline__ void mma_tf32(float* d, const uint32_t* a, const uint32_t* b) {
    asm volatile(
        "mma.sync.aligned.m16n8k8.row.col.f32.tf32.tf32.f32 "
        "{%0,%1,%2,%3}, {%4,%5,%6,%7}, {%8,%9}, {%0,%1,%2,%3};"
        : "+f"(d[0]), "+f"(d[1]), "+f"(d[2]), "+f"(d[3])
        : "r"(a[0]), "r"(a[1]), "r"(a[2]), "r"(a[3]), "r"(b[0]), "r"(b[1]));
}

// ============================================================================
// Weight transpose
// ============================================================================
__global__ void transpose32(const float* __restrict__ in, float* __restrict__ out,
                            int R, int C)
{
    __shared__ float t[32][33];
    const int bc = blockIdx.x * 32, br = blockIdx.y * 32;
    const int tx = threadIdx.x;
    for (int i = threadIdx.y; i < 32; i += 8)
        t[i][tx] = in[(size_t)(br + i) * C + bc + tx];
    __syncthreads();
    for (int i = threadIdx.y; i < 32; i += 8)
        out[(size_t)(bc + i) * R + br + tx] = t[tx][i];
}

// ============================================================================
// tf32 mma.sync GEMM (unchanged, passing @ 278us / 40% tensor)
// ============================================================================
#define BK      32
#define GPAD    36
#define TILE_F  (128 * GPAD)
#define G_SMEM  (4 * TILE_F * 4)

__global__ __launch_bounds__(256) void gemm_mma(
    const float* __restrict__ A, const float* __restrict__ Bt,
    float* __restrict__ C, int M, int N, int K)
{
    extern __shared__ float sm[];
    float* As = sm;
    float* Bs = sm + 2 * TILE_F;

    const int tid = threadIdx.x;
    const int wid = tid >> 5, lane = tid & 31;
    const int g   = lane >> 2;
    const int tg  = lane & 3;
    const int wm  = wid & 3;
    const int wn  = wid >> 2;
    const int m0  = blockIdx.y * 128, n0 = blockIdx.x * 128;

    const float* Ab = A  + (size_t)m0 * K;
    const float* Bb = Bt + (size_t)n0 * K;

    const int lrow[4] = { tid >> 3, (tid + 256) >> 3, (tid + 512) >> 3, (tid + 768) >> 3 };
    const int lcol    = (tid & 7) * 4;

    float acc[2][8][4];
    #pragma unroll
    for (int mt = 0; mt < 2; ++mt)
        #pragma unroll
        for (int nt = 0; nt < 8; ++nt)
            #pragma unroll
            for (int v = 0; v < 4; ++v) acc[mt][nt][v] = 0.f;

    const int NC = K / BK;
    float4 ra[4], rb[4];

    #pragma unroll
    for (int i = 0; i < 4; ++i) {
        ra[i] = *(const float4*)(Ab + (size_t)lrow[i] * K + lcol);
        rb[i] = *(const float4*)(Bb + (size_t)lrow[i] * K + lcol);
    }
    #pragma unroll
    for (int i = 0; i < 4; ++i) {
        float* pa = As + lrow[i] * GPAD + lcol;
        pa[0] = to_tf32(ra[i].x); pa[1] = to_tf32(ra[i].y);
        pa[2] = to_tf32(ra[i].z); pa[3] = to_tf32(ra[i].w);
        float* pb = Bs + lrow[i] * GPAD + lcol;
        pb[0] = to_tf32(rb[i].x); pb[1] = to_tf32(rb[i].y);
        pb[2] = to_tf32(rb[i].z); pb[3] = to_tf32(rb[i].w);
    }
    __syncthreads();

    for (int c = 0; c < NC; ++c) {
        const int s = c & 1;
        if (c + 1 < NC) {
            const int k0 = (c + 1) * BK;
            #pragma unroll
            for (int i = 0; i < 4; ++i) {
                ra[i] = *(const float4*)(Ab + (size_t)lrow[i] * K + k0 + lcol);
                rb[i] = *(const float4*)(Bb + (size_t)lrow[i] * K + k0 + lcol);
            }
        }
        const float* Ac = As + s * TILE_F;
        const float* Bc = Bs + s * TILE_F;
        #pragma unroll
        for (int ks = 0; ks < 4; ++ks) {
            const int k0 = ks * 8;
            uint32_t af[2][4], bf[8][2];
            #pragma unroll
            for (int mt = 0; mt < 2; ++mt) {
                const float* p = Ac + (wm * 32 + mt * 16 + g) * GPAD + k0 + tg;
                af[mt][0] = __float_as_uint(p[0]);
                af[mt][1] = __float_as_uint(p[8 * GPAD]);
                af[mt][2] = __float_as_uint(p[4]);
                af[mt][3] = __float_as_uint(p[8 * GPAD + 4]);
            }
            #pragma unroll
            for (int nt = 0; nt < 8; ++nt) {
                const float* p = Bc + (wn * 64 + nt * 8 + g) * GPAD + k0 + tg;
                bf[nt][0] = __float_as_uint(p[0]);
                bf[nt][1] = __float_as_uint(p[4]);
            }
            #pragma unroll
            for (int mt = 0; mt < 2; ++mt)
                #pragma unroll
                for (int nt = 0; nt < 8; ++nt)
                    mma_tf32(acc[mt][nt], af[mt], bf[nt]);
        }
        if (c + 1 < NC) {
            float* An = As + (s ^ 1) * TILE_F;
            float* Bn = Bs + (s ^ 1) * TILE_F;
            #pragma unroll
            for (int i = 0; i < 4; ++i) {
                float* pa = An + lrow[i] * GPAD + lcol;
                pa[0] = to_tf32(ra[i].x); pa[1] = to_tf32(ra[i].y);
                pa[2] = to_tf32(ra[i].z); pa[3] = to_tf32(ra[i].w);
                float* pb = Bn + lrow[i] * GPAD + lcol;
                pb[0] = to_tf32(rb[i].x); pb[1] = to_tf32(rb[i].y);
                pb[2] = to_tf32(rb[i].z); pb[3] = to_tf32(rb[i].w);
            }
            __syncthreads();
        }
    }

    #pragma unroll
    for (int mt = 0; mt < 2; ++mt) {
        const int row = m0 + wm * 32 + mt * 16 + g;
        #pragma unroll
        for (int nt = 0; nt < 8; ++nt) {
            const int col = n0 + wn * 64 + nt * 8 + 2 * tg;
            *(float2*)(C + (size_t)row * N + col) =
                make_float2(acc[mt][nt][0], acc[mt][nt][1]);
            *(float2*)(C + (size_t)(row + 8) * N + col) =
                make_float2(acc[mt][nt][2], acc[mt][nt][3]);
        }
    }
}

// ============================================================================
// RoPE (unchanged, passing)
// ============================================================================
__global__ void rope_kernel(float* __restrict__ qb, float* __restrict__ kvb,
                            const float* __restrict__ cb, const float* __restrict__ sb)
{
    const int QP = NTOK * (DIMM / 2);
    const int KP = NTOK * ((NKV * HD) / 2);
    int idx = blockIdx.x * blockDim.x + threadIdx.x;
    if (idx < QP) {
        int row = idx >> 10;
        int pc  = idx & 1023;
        int i   = pc & 31;
        int n   = row & (SEQ - 1);
        float c = cb[n * 32 + i], s = sb[n * 32 + i];
        float* p = qb + (size_t)row * DIMM + (pc >> 5) * HD + 2 * i;
        float xe = p[0], xo = p[1];
        p[0] = xe * c - xo * s;
        p[1] = xe * s + xo * c;
    } else if (idx < QP + KP) {
        int t   = idx - QP;
        int row = t >> 8;
        int pc  = t & 255;
        int i   = pc & 31;
        int n   = row & (SEQ - 1);
        float c = cb[n * 32 + i], s = sb[n * 32 + i];
        float* p = kvb + (size_t)row * KVC + (pc >> 5) * HD + 2 * i;
        float xe = p[0], xo = p[1];
        p[0] = xe * c - xo * s;
        p[1] = xe * s + xo * c;
    }
}

// ============================================================================
// Tensor-core causal flash attention (tf32 mma.sync), GQA h -> h % 8.
// CTA: 128 queries x one (b,h). 8 warps x 16 q-rows. Key tiles of 64.
// Q held as mma fragments in registers; softmax fully in registers;
// P round-trips through per-warp-private smem rows.
// Smem rows padded to 72 floats: all fragment patterns conflict-free.
// ============================================================================
#define FPAD   72
#define F2_SMEM ((128 * FPAD + 64 * FPAD + 64 * FPAD) * 4)   // Ps + Ks + Vs = 73728B
#define QTB    (SEQ / 128)    // 16

__global__ __launch_bounds__(256) void flash_mma(
    const float* __restrict__ q, const float* __restrict__ kv,
    float* __restrict__ o)
{
    extern __shared__ float fsm[];
    float* Ps = fsm;                    // [128][FPAD]  (Q staging, then P)
    float* Ks = fsm + 128 * FPAD;       // [64][FPAD]
    float* Vs = Ks + 64 * FPAD;         // [64][FPAD]

    const int qtb = (QTB - 1) - blockIdx.x;   // big tiles first (load balance)
    const int h = blockIdx.y, b = blockIdx.z;
    const int kvh = h & (NKV - 1);
    const int tid = threadIdx.x;
    const int wid = tid >> 5, lane = tid & 31;
    const int g = lane >> 2, tg = lane & 3;
    const int wrow = wid * 16;
    const int q0 = qtb * 128;

    // ---- stage Q (scaled 1/8, tf32) into Ps ----
    #pragma unroll
    for (int i = 0; i < 8; ++i) {
        int idx = tid + i * 256;           // 0..2047
        int row = idx >> 4, c4 = (idx & 15) * 4;
        float4 t = *(const float4*)(q + (size_t)(b * SEQ + q0 + row) * DIMM + h * HD + c4);
        float* p = Ps + row * FPAD + c4;
        p[0] = to_tf32(t.x * 0.125f); p[1] = to_tf32(t.y * 0.125f);
        p[2] = to_tf32(t.z * 0.125f); p[3] = to_tf32(t.w * 0.125f);
    }
    __syncthreads();

    // ---- Q fragments: 8 k-steps x 4 regs ----
    uint32_t qf[8][4];
    #pragma unroll
    for (int ks = 0; ks < 8; ++ks) {
        const float* p = Ps + (wrow + g) * FPAD + ks * 8 + tg;
        qf[ks][0] = __float_as_uint(p[0]);
        qf[ks][1] = __float_as_uint(p[8 * FPAD]);
        qf[ks][2] = __float_as_uint(p[4]);
        qf[ks][3] = __float_as_uint(p[8 * FPAD + 4]);
    }

    float m_g = -1e30f, m_g8 = -1e30f, l_g = 0.f, l_g8 = 0.f;
    float acc[8][4];
    #pragma unroll
    for (int nt = 0; nt < 8; ++nt)
        #pragma unroll
        for (int v = 0; v < 4; ++v) acc[nt][v] = 0.f;

    const int ktmax = 2 * qtb + 1;
    for (int kt = 0; kt <= ktmax; ++kt) {
        // prefetch K/V tile into regs
        float4 kr[4], vr[4];
        #pragma unroll
        for (int i = 0; i < 4; ++i) {
            int idx = tid + i * 256;       // 0..1023
            int row = idx >> 4, c4 = (idx & 15) * 4;
            const float* src = kv + (size_t)(b * SEQ + kt * 64 + row) * KVC + kvh * HD + c4;
            kr[i] = *(const float4*)src;
            vr[i] = *(const float4*)(src + 512);
        }
        __syncthreads();   // previous iteration's PV reads of Ks/Vs done
        #pragma unroll
        for (int i = 0; i < 4; ++i) {
            int idx = tid + i * 256;
            int row = idx >> 4, c4 = (idx & 15) * 4;
            float* pk = Ks + row * FPAD + c4;
            pk[0] = to_tf32(kr[i].x); pk[1] = to_tf32(kr[i].y);
            pk[2] = to_tf32(kr[i].z); pk[3] = to_tf32(kr[i].w);
            float* pv = Vs + row * FPAD + c4;
            pv[0] = to_tf32(vr[i].x); pv[1] = to_tf32(vr[i].y);
            pv[2] = to_tf32(vr[i].z); pv[3] = to_tf32(vr[i].w);
        }
        __syncthreads();

        // ---- S = Q @ K^T ----
        float sA[8][4];
        #pragma unroll
        for (int nt = 0; nt < 8; ++nt)
            #pragma unroll
            for (int v = 0; v < 4; ++v) sA[nt][v] = 0.f;
        #pragma unroll
        for (int ks = 0; ks < 8; ++ks) {
            uint32_t bf[8][2];
            #pragma unroll
            for (int nt = 0; nt < 8; ++nt) {
                const float* p = Ks + (nt * 8 + g) * FPAD + ks * 8 + tg;
                bf[nt][0] = __float_as_uint(p[0]);
                bf[nt][1] = __float_as_uint(p[4]);
            }
            #pragma unroll
            for (int nt = 0; nt < 8; ++nt)
                mma_tf32(sA[nt], qf[ks], bf[nt]);
        }

        // ---- causal mask (diagonal tiles only) ----
        if (kt >= 2 * qtb) {
            const int qr = q0 + wrow + g;
            const int kc0 = kt * 64;
            #pragma unroll
            for (int nt = 0; nt < 8; ++nt) {
                const int col = kc0 + nt * 8 + 2 * tg;
                if (col > qr)         sA[nt][0] = -1e30f;
                if (col + 1 > qr)     sA[nt][1] = -1e30f;
                if (col > qr + 8)     sA[nt][2] = -1e30f;
                if (col + 1 > qr + 8) sA[nt][3] = -1e30f;
            }
        }

        // ---- online softmax in registers ----
        float mxg = -1e30f, mxg8 = -1e30f;
        #pragma unroll
        for (int nt = 0; nt < 8; ++nt) {
            mxg  = fmaxf(mxg,  fmaxf(sA[nt][0], sA[nt][1]));
            mxg8 = fmaxf(mxg8, fmaxf(sA[nt][2], sA[nt][3]));
        }
        mxg  = fmaxf(mxg,  __shfl_xor_sync(0xffffffffu, mxg, 1));
        mxg  = fmaxf(mxg,  __shfl_xor_sync(0xffffffffu, mxg, 2));
        mxg8 = fmaxf(mxg8, __shfl_xor_sync(0xffffffffu, mxg8, 1));
        mxg8 = fmaxf(mxg8, __shfl_xor_sync(0xffffffffu, mxg8, 2));

        const float mn_g  = fmaxf(m_g,  mxg);
        const float mn_g8 = fmaxf(m_g8, mxg8);
        const float cr_g  = __expf(m_g  - mn_g);
        const float cr_g8 = __expf(m_g8 - mn_g8);

        float sum_g = 0.f, sum_g8 = 0.f;
        #pragma unroll
        for (int nt = 0; nt < 8; ++nt) {
            sA[nt][0] = __expf(sA[nt][0] - mn_g);
            sA[nt][1] = __expf(sA[nt][1] - mn_g);
            sA[nt][2] = __expf(sA[nt][2] - mn_g8);
            sA[nt][3] = __expf(sA[nt][3] - mn_g8);
            sum_g  += sA[nt][0] + sA[nt][1];
            sum_g8 += sA[nt][2] + sA[nt][3];
        }
        sum_g  += __shfl_xor_sync(0xffffffffu, sum_g, 1);
        sum_g  += __shfl_xor_sync(0xffffffffu, sum_g, 2);
        sum_g8 += __shfl_xor_sync(0xffffffffu, sum_g8, 1);
        sum_g8 += __shfl_xor_sync(0xffffffffu, sum_g8, 2);

        m_g = mn_g;  l_g  = l_g  * cr_g  + sum_g;
        m_g8 = mn_g8; l_g8 = l_g8 * cr_g8 + sum_g8;

        // ---- P -> smem (tf32); per-warp-private rows ----
        {
            float* pr = Ps + (wrow + g) * FPAD;
            #pragma unroll
            for (int nt = 0; nt < 8; ++nt) {
                *(float2*)(pr + nt * 8 + 2 * tg) =
                    make_float2(to_tf32(sA[nt][0]), to_tf32(sA[nt][1]));
                *(float2*)(pr + 8 * FPAD + nt * 8 + 2 * tg) =
                    make_float2(to_tf32(sA[nt][2]), to_tf32(sA[nt][3]));
            }
        }
        __syncwarp();

        // ---- rescale acc ----
        #pragma unroll
        for (int nt = 0; nt < 8; ++nt) {
            acc[nt][0] *= cr_g;  acc[nt][1] *= cr_g;
            acc[nt][2] *= cr_g8; acc[nt][3] *= cr_g8;
        }

        // ---- O += P @ V ----
        #pragma unroll
        for (int ks = 0; ks < 8; ++ks) {
            uint32_t af[4];
            {
                const float* p = Ps + (wrow + g) * FPAD + ks * 8 + tg;
                af[0] = __float_as_uint(p[0]);
                af[1] = __float_as_uint(p[8 * FPAD]);
                af[2] = __float_as_uint(p[4]);
                af[3] = __float_as_uint(p[8 * FPAD + 4]);
            }
            uint32_t bf[8][2];
            #pragma unroll
            for (int nt = 0; nt < 8; ++nt) {
                const float* p = Vs + (ks * 8 + tg) * FPAD + nt * 8 + g;
                bf[nt][0] = __float_as_uint(p[0]);
                bf[nt][1] = __float_as_uint(p[4 * FPAD]);
            }
            #pragma unroll
            for (int nt = 0; nt < 8; ++nt)
                mma_tf32(acc[nt], af, bf[nt]);
        }
    }

    // ---- epilogue: normalize, write (b, n, h*64+d) ----
    const float il_g = 1.f / l_g, il_g8 = 1.f / l_g8;
    float* ob  = o + (size_t)(b * SEQ + q0 + wrow + g) * DIMM + h * HD;
    float* ob8 = ob + 8 * DIMM;
    #pragma unroll
    for (int nt = 0; nt < 8; ++nt) {
        const int col = nt * 8 + 2 * tg;
        *(float2*)(ob + col)  = make_float2(acc[nt][0] * il_g,  acc[nt][1] * il_g);
        *(float2*)(ob8 + col) = make_float2(acc[nt][2] * il_g8, acc[nt][3] * il_g8);
    }
}

// ============================================================================
extern "C" void kernel_launch(void* const* d_in, const int* in_sizes, int n_in,
                              void* d_out, int out_size)
{
    const float* x   = (const float*)d_in[0];
    const float* Wq  = (const float*)d_in[1];
    const float* Wkv = (const float*)d_in[2];
    const float* Wo  = (const float*)d_in[3];
    const float* cb  = (const float*)d_in[4];
    const float* sb  = (const float*)d_in[5];
    float* out = (float*)d_out;

    float *qb, *kvb, *ab, *wqt, *wkvt, *wot;
    cudaGetSymbolAddress((void**)&qb,   g_q);
    cudaGetSymbolAddress((void**)&kvb,  g_kv);
    cudaGetSymbolAddress((void**)&ab,   g_att);
    cudaGetSymbolAddress((void**)&wqt,  g_wqt);
    cudaGetSymbolAddress((void**)&wkvt, g_wkvt);
    cudaGetSymbolAddress((void**)&wot,  g_wot);

    cudaFuncSetAttribute(gemm_mma,
                         cudaFuncAttributeMaxDynamicSharedMemorySize, G_SMEM);
    cudaFuncSetAttribute(flash_mma,
                         cudaFuncAttributeMaxDynamicSharedMemorySize, F2_SMEM);

    // transpose weights to [N][K]
    transpose32<<<dim3(DIMM / 32, DIMM / 32), dim3(32, 8)>>>(Wq, wqt, DIMM, DIMM);
    transpose32<<<dim3(KVC / 32, DIMM / 32), dim3(32, 8)>>>(Wkv, wkvt, DIMM, KVC);
    transpose32<<<dim3(DIMM / 32, DIMM / 32), dim3(32, 8)>>>(Wo, wot, DIMM, DIMM);

    // Q = x @ Wq
    gemm_mma<<<dim3(DIMM / 128, NTOK / 128), 256, G_SMEM>>>(x, wqt, qb, NTOK, DIMM, DIMM);
    // KV = x @ Wkv
    gemm_mma<<<dim3(KVC / 128, NTOK / 128), 256, G_SMEM>>>(x, wkvt, kvb, NTOK, KVC, DIMM);
    // RoPE
    {
        int totalPairs = NTOK * (DIMM / 2) + NTOK * ((NKV * HD) / 2);
        rope_kernel<<<(totalPairs + 255) / 256, 256>>>(qb, kvb, cb, sb);
    }
    // tensor-core causal GQA flash attention
    flash_mma<<<dim3(QTB, NH, BATCH), 256, F2_SMEM>>>(qb, kvb, ab);
    // out = att @ Wo
    gemm_mma<<<dim3(DIMM / 128, NTOK / 128), 256, G_SMEM>>>(ab, wot, out, NTOK, DIMM, DIMM);
}

// round 5
// speedup vs baseline: 5.2369x; 1.0824x over previous
#include <cuda_runtime.h>
#include <cstdint>

#define SEQ   2048
#define BATCH 2
#define NTOK  (SEQ * BATCH)      // 4096
#define DIMM  2048
#define NH    32
#define NKV   8
#define HD    64
#define KVC   (2 * NKV * HD)     // 1024: cols [0,512)=K, [512,1024)=V

// ---- scratch (static device globals: allocation-free) ----
__device__ float g_x[(size_t)NTOK * DIMM];    // x rounded to tf32
__device__ float g_q[(size_t)NTOK * DIMM];
__device__ float g_kv[(size_t)NTOK * KVC];
__device__ float g_att[(size_t)NTOK * DIMM];
__device__ float g_wqt[(size_t)DIMM * DIMM];
__device__ float g_wkvt[(size_t)KVC * DIMM];
__device__ float g_wot[(size_t)DIMM * DIMM];

__device__ __forceinline__ float to_tf32(float x) {
    float y;
    asm("cvt.rna.tf32.f32 %0, %1;" : "=f"(y) : "f"(x));
    return y;
}
__device__ __forceinline__ uint32_t smem_u32(const void* p) {
    uint32_t a;
    asm("{ .reg .u64 t; cvta.to.shared.u64 t, %1; cvt.u32.u64 %0, t; }" : "=r"(a) : "l"(p));
    return a;
}
__device__ __forceinline__ void mma_tf32(float* d, const uint32_t* a, const uint32_t* b) {
    asm volatile(
        "mma.sync.aligned.m16n8k8.row.col.f32.tf32.tf32.f32 "
        "{%0,%1,%2,%3}, {%4,%5,%6,%7}, {%8,%9}, {%0,%1,%2,%3};"
        : "+f"(d[0]), "+f"(d[1]), "+f"(d[2]), "+f"(d[3])
        : "r"(a[0]), "r"(a[1]), "r"(a[2]), "r"(a[3]), "r"(b[0]), "r"(b[1]));
}
__device__ __forceinline__ void cp16(uint32_t dst, const float* src) {
    asm volatile("cp.async.cg.shared.global [%0], [%1], 16;" :: "r"(dst), "l"(src));
}

// ============================================================================
// Round fp32 -> tf32 values (vectorized)
// ============================================================================
__global__ void round_tf32(const float* __restrict__ in, float* __restrict__ out, int n4)
{
    int i = blockIdx.x * blockDim.x + threadIdx.x;
    if (i < n4) {
        float4 t = ((const float4*)in)[i];
        t.x = to_tf32(t.x); t.y = to_tf32(t.y);
        t.z = to_tf32(t.z); t.w = to_tf32(t.w);
        ((float4*)out)[i] = t;
    }
}

// ============================================================================
// Weight transpose (rounds to tf32 on store)
// ============================================================================
__global__ void transpose32(const float* __restrict__ in, float* __restrict__ out,
                            int R, int C)
{
    __shared__ float t[32][33];
    const int bc = blockIdx.x * 32, br = blockIdx.y * 32;
    const int tx = threadIdx.x;
    for (int i = threadIdx.y; i < 32; i += 8)
        t[i][tx] = in[(size_t)(br + i) * C + bc + tx];
    __syncthreads();
    for (int i = threadIdx.y; i < 32; i += 8)
        out[(size_t)(bc + i) * R + br + tx] = to_tf32(t[tx][i]);
}

// ============================================================================
// tf32 mma.sync GEMM v2: C(M,N) = A(M,K) @ Bt(N,K)^T, inputs pre-rounded tf32.
// 128 threads (4 warps, 2M x 2N), CTA tile 128x128, warp tile 64x64, BK=32.
// 2-stage cp.async pipeline; no cvt in hot loop. 2 CTAs/SM.
// ============================================================================
#define G2PAD  36
#define G2TILE (128 * G2PAD)          // floats per operand per stage
#define G2_SMEM (4 * G2TILE * 4)      // A0,A1,B0,B1 = 73728 B

__global__ __launch_bounds__(128) void gemm_mma2(
    const float* __restrict__ A, const float* __restrict__ Bt,
    float* __restrict__ C, int M, int N, int K, int roundC)
{
    extern __shared__ float sm2[];
    const uint32_t sbase = smem_u32(sm2);
    const int tid = threadIdx.x;
    const int wid = tid >> 5, lane = tid & 31;
    const int g = lane >> 2, tg = lane & 3;
    const int wm = wid & 1, wn = wid >> 1;
    const int m0 = blockIdx.y * 128, n0 = blockIdx.x * 128;

    const float* Ab = A + (size_t)m0 * K;
    const float* Bb = Bt + (size_t)n0 * K;

    const int lrow = tid >> 3;          // 0..15
    const int lcol = (tid & 7) * 4;     // float col

    float acc[4][8][4];
    #pragma unroll
    for (int mt = 0; mt < 4; ++mt)
        #pragma unroll
        for (int nt = 0; nt < 8; ++nt)
            #pragma unroll
            for (int v = 0; v < 4; ++v) acc[mt][nt][v] = 0.f;

    const int NC = K / 32;

    auto issue_chunk = [&](int s, int k0) {
        const uint32_t abase = sbase + (uint32_t)(s * G2TILE) * 4u;
        const uint32_t bbase = sbase + (uint32_t)((2 + s) * G2TILE) * 4u;
        #pragma unroll
        for (int i = 0; i < 8; ++i) {
            const int row = lrow + i * 16;
            const uint32_t doff = (uint32_t)(row * G2PAD + lcol) * 4u;
            cp16(abase + doff, Ab + (size_t)row * K + k0 + lcol);
            cp16(bbase + doff, Bb + (size_t)row * K + k0 + lcol);
        }
        asm volatile("cp.async.commit_group;" ::: "memory");
    };

    issue_chunk(0, 0);

    for (int c = 0; c < NC; ++c) {
        const int s = c & 1;
        if (c + 1 < NC) {
            issue_chunk(s ^ 1, (c + 1) * 32);
            asm volatile("cp.async.wait_group 1;" ::: "memory");
        } else {
            asm volatile("cp.async.wait_group 0;" ::: "memory");
        }
        __syncthreads();

        const float* As = sm2 + s * G2TILE;
        const float* Bs = sm2 + (2 + s) * G2TILE;
        #pragma unroll
        for (int ks = 0; ks < 4; ++ks) {
            const int k0 = ks * 8;
            uint32_t af[4][4], bf[8][2];
            #pragma unroll
            for (int mt = 0; mt < 4; ++mt) {
                const float* p = As + (wm * 64 + mt * 16 + g) * G2PAD + k0 + tg;
                af[mt][0] = __float_as_uint(p[0]);
                af[mt][1] = __float_as_uint(p[8 * G2PAD]);
                af[mt][2] = __float_as_uint(p[4]);
                af[mt][3] = __float_as_uint(p[8 * G2PAD + 4]);
            }
            #pragma unroll
            for (int nt = 0; nt < 8; ++nt) {
                const float* p = Bs + (wn * 64 + nt * 8 + g) * G2PAD + k0 + tg;
                bf[nt][0] = __float_as_uint(p[0]);
                bf[nt][1] = __float_as_uint(p[4]);
            }
            #pragma unroll
            for (int mt = 0; mt < 4; ++mt)
                #pragma unroll
                for (int nt = 0; nt < 8; ++nt)
                    mma_tf32(acc[mt][nt], af[mt], bf[nt]);
        }
        __syncthreads();
    }

    #pragma unroll
    for (int mt = 0; mt < 4; ++mt) {
        const int row = m0 + wm * 64 + mt * 16 + g;
        #pragma unroll
        for (int nt = 0; nt < 8; ++nt) {
            const int col = n0 + wn * 64 + nt * 8 + 2 * tg;
            float2 v0 = make_float2(acc[mt][nt][0], acc[mt][nt][1]);
            float2 v1 = make_float2(acc[mt][nt][2], acc[mt][nt][3]);
            if (roundC) {
                v0.x = to_tf32(v0.x); v0.y = to_tf32(v0.y);
                v1.x = to_tf32(v1.x); v1.y = to_tf32(v1.y);
            }
            *(float2*)(C + (size_t)row * N + col) = v0;
            *(float2*)(C + (size_t)(row + 8) * N + col) = v1;
        }
    }
}

// ============================================================================
// RoPE (writes tf32-rounded values)
// ============================================================================
__global__ void rope_kernel(float* __restrict__ qb, float* __restrict__ kvb,
                            const float* __restrict__ cb, const float* __restrict__ sb)
{
    const int QP = NTOK * (DIMM / 2);
    const int KP = NTOK * ((NKV * HD) / 2);
    int idx = blockIdx.x * blockDim.x + threadIdx.x;
    if (idx < QP) {
        int row = idx >> 10;
        int pc  = idx & 1023;
        int i   = pc & 31;
        int n   = row & (SEQ - 1);
        float c = cb[n * 32 + i], s = sb[n * 32 + i];
        float* p = qb + (size_t)row * DIMM + (pc >> 5) * HD + 2 * i;
        float xe = p[0], xo = p[1];
        p[0] = to_tf32(xe * c - xo * s);
        p[1] = to_tf32(xe * s + xo * c);
    } else if (idx < QP + KP) {
        int t   = idx - QP;
        int row = t >> 8;
        int pc  = t & 255;
        int i   = pc & 31;
        int n   = row & (SEQ - 1);
        float c = cb[n * 32 + i], s = sb[n * 32 + i];
        float* p = kvb + (size_t)row * KVC + (pc >> 5) * HD + 2 * i;
        float xe = p[0], xo = p[1];
        p[0] = to_tf32(xe * c - xo * s);
        p[1] = to_tf32(xe * s + xo * c);
    }
}

// ============================================================================
// Tensor-core causal flash attention (tf32 mma.sync), GQA h -> h % 8.
// Inputs pre-rounded tf32 (Q/K via rope, V via gemm epilogue).
// Next KV tile prefetched into regs before compute (global latency hidden).
// ============================================================================
#define FPAD   72
#define F2_SMEM ((128 * FPAD + 64 * FPAD + 64 * FPAD) * 4)
#define QTB    (SEQ / 128)    // 16

__global__ __launch_bounds__(256) void flash_mma(
    const float* __restrict__ q, const float* __restrict__ kv,
    float* __restrict__ o)
{
    extern __shared__ float fsm[];
    float* Ps = fsm;                    // [128][FPAD]  (Q staging, then P)
    float* Ks = fsm + 128 * FPAD;       // [64][FPAD]
    float* Vs = Ks + 64 * FPAD;         // [64][FPAD]

    const int qtb = (QTB - 1) - blockIdx.x;   // big tiles first
    const int h = blockIdx.y, b = blockIdx.z;
    const int kvh = h & (NKV - 1);
    const int tid = threadIdx.x;
    const int wid = tid >> 5, lane = tid & 31;
    const int g = lane >> 2, tg = lane & 3;
    const int wrow = wid * 16;
    const int q0 = qtb * 128;

    // ---- stage Q (scaled 1/8 exact; already tf32) ----
    #pragma unroll
    for (int i = 0; i < 8; ++i) {
        int idx = tid + i * 256;
        int row = idx >> 4, c4 = (idx & 15) * 4;
        float4 t = *(const float4*)(q + (size_t)(b * SEQ + q0 + row) * DIMM + h * HD + c4);
        float* p = Ps + row * FPAD + c4;
        p[0] = t.x * 0.125f; p[1] = t.y * 0.125f;
        p[2] = t.z * 0.125f; p[3] = t.w * 0.125f;
    }
    __syncthreads();

    // ---- Q fragments ----
    uint32_t qf[8][4];
    #pragma unroll
    for (int ks = 0; ks < 8; ++ks) {
        const float* p = Ps + (wrow + g) * FPAD + ks * 8 + tg;
        qf[ks][0] = __float_as_uint(p[0]);
        qf[ks][1] = __float_as_uint(p[8 * FPAD]);
        qf[ks][2] = __float_as_uint(p[4]);
        qf[ks][3] = __float_as_uint(p[8 * FPAD + 4]);
    }

    float m_g = -1e30f, m_g8 = -1e30f, l_g = 0.f, l_g8 = 0.f;
    float acc[8][4];
    #pragma unroll
    for (int nt = 0; nt < 8; ++nt)
        #pragma unroll
        for (int v = 0; v < 4; ++v) acc[nt][v] = 0.f;

    const int ktmax = 2 * qtb + 1;

    // prologue: load tile 0 into regs
    float4 kr[4], vr[4];
    #pragma unroll
    for (int i = 0; i < 4; ++i) {
        int idx = tid + i * 256;
        int row = idx >> 4, c4 = (idx & 15) * 4;
        const float* src = kv + (size_t)(b * SEQ + row) * KVC + kvh * HD + c4;
        kr[i] = *(const float4*)src;
        vr[i] = *(const float4*)(src + 512);
    }

    for (int kt = 0; kt <= ktmax; ++kt) {
        __syncthreads();   // previous compute done reading Ks/Vs
        #pragma unroll
        for (int i = 0; i < 4; ++i) {
            int idx = tid + i * 256;
            int row = idx >> 4, c4 = (idx & 15) * 4;
            float* pk = Ks + row * FPAD + c4;
            pk[0] = kr[i].x; pk[1] = kr[i].y; pk[2] = kr[i].z; pk[3] = kr[i].w;
            float* pv = Vs + row * FPAD + c4;
            pv[0] = vr[i].x; pv[1] = vr[i].y; pv[2] = vr[i].z; pv[3] = vr[i].w;
        }
        __syncthreads();

        // prefetch next tile (latency hidden under compute)
        if (kt < ktmax) {
            #pragma unroll
            for (int i = 0; i < 4; ++i) {
                int idx = tid + i * 256;
                int row = idx >> 4, c4 = (idx & 15) * 4;
                const float* src = kv + (size_t)(b * SEQ + (kt + 1) * 64 + row) * KVC + kvh * HD + c4;
                kr[i] = *(const float4*)src;
                vr[i] = *(const float4*)(src + 512);
            }
        }

        // ---- S = Q @ K^T ----
        float sA[8][4];
        #pragma unroll
        for (int nt = 0; nt < 8; ++nt)
            #pragma unroll
            for (int v = 0; v < 4; ++v) sA[nt][v] = 0.f;
        #pragma unroll
        for (int ks = 0; ks < 8; ++ks) {
            uint32_t bf[8][2];
            #pragma unroll
            for (int nt = 0; nt < 8; ++nt) {
                const float* p = Ks + (nt * 8 + g) * FPAD + ks * 8 + tg;
                bf[nt][0] = __float_as_uint(p[0]);
                bf[nt][1] = __float_as_uint(p[4]);
            }
            #pragma unroll
            for (int nt = 0; nt < 8; ++nt)
                mma_tf32(sA[nt], qf[ks], bf[nt]);
        }

        // ---- causal mask (diagonal tiles) ----
        if (kt >= 2 * qtb) {
            const int qr = q0 + wrow + g;
            const int kc0 = kt * 64;
            #pragma unroll
            for (int nt = 0; nt < 8; ++nt) {
                const int col = kc0 + nt * 8 + 2 * tg;
                if (col > qr)         sA[nt][0] = -1e30f;
                if (col + 1 > qr)     sA[nt][1] = -1e30f;
                if (col > qr + 8)     sA[nt][2] = -1e30f;
                if (col + 1 > qr + 8) sA[nt][3] = -1e30f;
            }
        }

        // ---- online softmax in registers ----
        float mxg = -1e30f, mxg8 = -1e30f;
        #pragma unroll
        for (int nt = 0; nt < 8; ++nt) {
            mxg  = fmaxf(mxg,  fmaxf(sA[nt][0], sA[nt][1]));
            mxg8 = fmaxf(mxg8, fmaxf(sA[nt][2], sA[nt][3]));
        }
        mxg  = fmaxf(mxg,  __shfl_xor_sync(0xffffffffu, mxg, 1));
        mxg  = fmaxf(mxg,  __shfl_xor_sync(0xffffffffu, mxg, 2));
        mxg8 = fmaxf(mxg8, __shfl_xor_sync(0xffffffffu, mxg8, 1));
        mxg8 = fmaxf(mxg8, __shfl_xor_sync(0xffffffffu, mxg8, 2));

        const float mn_g  = fmaxf(m_g,  mxg);
        const float mn_g8 = fmaxf(m_g8, mxg8);
        const float cr_g  = __expf(m_g  - mn_g);
        const float cr_g8 = __expf(m_g8 - mn_g8);

        float sum_g = 0.f, sum_g8 = 0.f;
        #pragma unroll
        for (int nt = 0; nt < 8; ++nt) {
            sA[nt][0] = __expf(sA[nt][0] - mn_g);
            sA[nt][1] = __expf(sA[nt][1] - mn_g);
            sA[nt][2] = __expf(sA[nt][2] - mn_g8);
            sA[nt][3] = __expf(sA[nt][3] - mn_g8);
            sum_g  += sA[nt][0] + sA[nt][1];
            sum_g8 += sA[nt][2] + sA[nt][3];
        }
        sum_g  += __shfl_xor_sync(0xffffffffu, sum_g, 1);
        sum_g  += __shfl_xor_sync(0xffffffffu, sum_g, 2);
        sum_g8 += __shfl_xor_sync(0xffffffffu, sum_g8, 1);
        sum_g8 += __shfl_xor_sync(0xffffffffu, sum_g8, 2);

        m_g = mn_g;  l_g  = l_g  * cr_g  + sum_g;
        m_g8 = mn_g8; l_g8 = l_g8 * cr_g8 + sum_g8;

        // ---- P -> smem (tf32); per-warp-private rows ----
        {
            float* pr = Ps + (wrow + g) * FPAD;
            #pragma unroll
            for (int nt = 0; nt < 8; ++nt) {
                *(float2*)(pr + nt * 8 + 2 * tg) =
                    make_float2(to_tf32(sA[nt][0]), to_tf32(sA[nt][1]));
                *(float2*)(pr + 8 * FPAD + nt * 8 + 2 * tg) =
                    make_float2(to_tf32(sA[nt][2]), to_tf32(sA[nt][3]));
            }
        }
        __syncwarp();

        // ---- rescale acc ----
        #pragma unroll
        for (int nt = 0; nt < 8; ++nt) {
            acc[nt][0] *= cr_g;  acc[nt][1] *= cr_g;
            acc[nt][2] *= cr_g8; acc[nt][3] *= cr_g8;
        }

        // ---- O += P @ V ----
        #pragma unroll
        for (int ks = 0; ks < 8; ++ks) {
            uint32_t af[4];
            {
                const float* p = Ps + (wrow + g) * FPAD + ks * 8 + tg;
                af[0] = __float_as_uint(p[0]);
                af[1] = __float_as_uint(p[8 * FPAD]);
                af[2] = __float_as_uint(p[4]);
                af[3] = __float_as_uint(p[8 * FPAD + 4]);
            }
            uint32_t bf[8][2];
            #pragma unroll
            for (int nt = 0; nt < 8; ++nt) {
                const float* p = Vs + (ks * 8 + tg) * FPAD + nt * 8 + g;
                bf[nt][0] = __float_as_uint(p[0]);
                bf[nt][1] = __float_as_uint(p[4 * FPAD]);
            }
            #pragma unroll
            for (int nt = 0; nt < 8; ++nt)
                mma_tf32(acc[nt], af, bf[nt]);
        }
    }

    // ---- epilogue: normalize, write tf32-rounded (feeds O-proj) ----
    const float il_g = 1.f / l_g, il_g8 = 1.f / l_g8;
    float* ob  = o + (size_t)(b * SEQ + q0 + wrow + g) * DIMM + h * HD;
    float* ob8 = ob + 8 * DIMM;
    #pragma unroll
    for (int nt = 0; nt < 8; ++nt) {
        const int col = nt * 8 + 2 * tg;
        *(float2*)(ob + col)  = make_float2(to_tf32(acc[nt][0] * il_g),
                                            to_tf32(acc[nt][1] * il_g));
        *(float2*)(ob8 + col) = make_float2(to_tf32(acc[nt][2] * il_g8),
                                            to_tf32(acc[nt][3] * il_g8));
    }
}

// ============================================================================
extern "C" void kernel_launch(void* const* d_in, const int* in_sizes, int n_in,
                              void* d_out, int out_size)
{
    const float* x   = (const float*)d_in[0];
    const float* Wq  = (const float*)d_in[1];
    const float* Wkv = (const float*)d_in[2];
    const float* Wo  = (const float*)d_in[3];
    const float* cb  = (const float*)d_in[4];
    const float* sb  = (const float*)d_in[5];
    float* out = (float*)d_out;

    float *xb, *qb, *kvb, *ab, *wqt, *wkvt, *wot;
    cudaGetSymbolAddress((void**)&xb,   g_x);
    cudaGetSymbolAddress((void**)&qb,   g_q);
    cudaGetSymbolAddress((void**)&kvb,  g_kv);
    cudaGetSymbolAddress((void**)&ab,   g_att);
    cudaGetSymbolAddress((void**)&wqt,  g_wqt);
    cudaGetSymbolAddress((void**)&wkvt, g_wkvt);
    cudaGetSymbolAddress((void**)&wot,  g_wot);

    cudaFuncSetAttribute(gemm_mma2,
                         cudaFuncAttributeMaxDynamicSharedMemorySize, G2_SMEM);
    cudaFuncSetAttribute(flash_mma,
                         cudaFuncAttributeMaxDynamicSharedMemorySize, F2_SMEM);

    // round x; transpose + round weights
    {
        int n4 = NTOK * DIMM / 4;
        round_tf32<<<(n4 + 255) / 256, 256>>>(x, xb, n4);
    }
    transpose32<<<dim3(DIMM / 32, DIMM / 32), dim3(32, 8)>>>(Wq, wqt, DIMM, DIMM);
    transpose32<<<dim3(KVC / 32, DIMM / 32), dim3(32, 8)>>>(Wkv, wkvt, DIMM, KVC);
    transpose32<<<dim3(DIMM / 32, DIMM / 32), dim3(32, 8)>>>(Wo, wot, DIMM, DIMM);

    // Q = x @ Wq ; KV = x @ Wkv  (outputs rounded to tf32)
    gemm_mma2<<<dim3(DIMM / 128, NTOK / 128), 128, G2_SMEM>>>(xb, wqt, qb, NTOK, DIMM, DIMM, 1);
    gemm_mma2<<<dim3(KVC / 128, NTOK / 128), 128, G2_SMEM>>>(xb, wkvt, kvb, NTOK, KVC, DIMM, 1);
    // RoPE (rounded writes)
    {
        int totalPairs = NTOK * (DIMM / 2) + NTOK * ((NKV * HD) / 2);
        rope_kernel<<<(totalPairs + 255) / 256, 256>>>(qb, kvb, cb, sb);
    }
    // tensor-core causal GQA flash attention
    flash_mma<<<dim3(QTB, NH, BATCH), 256, F2_SMEM>>>(qb, kvb, ab);
    // out = att @ Wo (unrounded output)
    gemm_mma2<<<dim3(DIMM / 128, NTOK / 128), 128, G2_SMEM>>>(ab, wot, out, NTOK, DIMM, DIMM, 0);
}

// round 6
// speedup vs baseline: 9.6843x; 1.8493x over previous
#include <cuda_runtime.h>
#include <cuda_fp16.h>
#include <cstdint>

#define SEQ   2048
#define BATCH 2
#define NTOK  (SEQ * BATCH)      // 4096
#define DIMM  2048
#define NH    32
#define NKV   8
#define HD    64
#define KVC   (2 * NKV * HD)     // 1024: cols [0,512)=K, [512,1024)=V

// ---- scratch (static device globals: allocation-free) ----
__device__ __half g_xh[(size_t)NTOK * DIMM];
__device__ float  g_q[(size_t)NTOK * DIMM];          // Q proj (pre-rope, fp32)
__device__ float  g_kv[(size_t)NTOK * KVC];          // KV proj (pre-rope, fp32)
__device__ __half g_qh[(size_t)NTOK * DIMM];         // Q after rope (half)
__device__ __half g_kh[(size_t)NTOK * NKV * HD];     // K after rope (half)
__device__ __half g_vt[(size_t)BATCH * NKV * HD * SEQ]; // V transposed [b][kvh][d][n]
__device__ __half g_ah[(size_t)NTOK * DIMM];         // attention out (half)
__device__ __half g_wqt[(size_t)DIMM * DIMM];
__device__ __half g_wkvt[(size_t)KVC * DIMM];
__device__ __half g_wot[(size_t)DIMM * DIMM];

__device__ __forceinline__ uint32_t smem_u32(const void* p) {
    uint32_t a;
    asm("{ .reg .u64 t; cvta.to.shared.u64 t, %1; cvt.u32.u64 %0, t; }" : "=r"(a) : "l"(p));
    return a;
}
__device__ __forceinline__ void mma_f16(float* d, const uint32_t* a, const uint32_t* b) {
    asm volatile(
        "mma.sync.aligned.m16n8k16.row.col.f32.f16.f16.f32 "
        "{%0,%1,%2,%3}, {%4,%5,%6,%7}, {%8,%9}, {%0,%1,%2,%3};"
        : "+f"(d[0]), "+f"(d[1]), "+f"(d[2]), "+f"(d[3])
        : "r"(a[0]), "r"(a[1]), "r"(a[2]), "r"(a[3]), "r"(b[0]), "r"(b[1]));
}
__device__ __forceinline__ void cp16(uint32_t dst, const void* src) {
    asm volatile("cp.async.cg.shared.global [%0], [%1], 16;" :: "r"(dst), "l"(src));
}

// ============================================================================
// x: fp32 -> fp16
// ============================================================================
__global__ void conv_x(const float* __restrict__ in, __half* __restrict__ out, int n2)
{
    int i = blockIdx.x * blockDim.x + threadIdx.x;
    if (i < n2) {
        float2 t = ((const float2*)in)[i];
        ((half2*)out)[i] = __floats2half2_rn(t.x, t.y);
    }
}

// ============================================================================
// Weight transpose fp32 -> fp16:  out[c][r] = half(in[r][c])
// ============================================================================
__global__ void transpose32h(const float* __restrict__ in, __half* __restrict__ out,
                             int R, int C)
{
    __shared__ float t[32][33];
    const int bc = blockIdx.x * 32, br = blockIdx.y * 32;
    const int tx = threadIdx.x;
    for (int i = threadIdx.y; i < 32; i += 8)
        t[i][tx] = in[(size_t)(br + i) * C + bc + tx];
    __syncthreads();
    for (int i = threadIdx.y; i < 32; i += 8)
        out[(size_t)(bc + i) * R + br + tx] = __float2half_rn(t[tx][i]);
}

// ============================================================================
// V transpose: g_kv V-half (fp32, [token][kvh*64+d]) -> g_vt (half, [b][kvh][d][n])
// ============================================================================
__global__ void transposeV(const float* __restrict__ kv, __half* __restrict__ vt)
{
    __shared__ float t[32][33];
    const int n0 = blockIdx.x * 32, d0 = blockIdx.y * 32;
    const int bk = blockIdx.z;                 // b*NKV + kvh
    const int b = bk >> 3, kvh = bk & 7;
    const int tx = threadIdx.x;
    for (int i = threadIdx.y; i < 32; i += 8)
        t[i][tx] = kv[(size_t)(b * SEQ + n0 + i) * KVC + 512 + kvh * HD + d0 + tx];
    __syncthreads();
    for (int i = threadIdx.y; i < 32; i += 8)
        vt[((size_t)bk * HD + d0 + i) * SEQ + n0 + tx] = __float2half_rn(t[tx][i]);
}

// ============================================================================
// fp16 mma.sync GEMM: C(M,N) = A(M,K) @ Bt(N,K)^T, fp32 accum/output.
// 128 threads (4 warps, 2M x 2N), CTA 128x128, warp 64x64, BK=64 halves.
// m16n8k16; cp.async 2-stage pipeline.
// ============================================================================
#define GPADH  72                        // halves per padded smem row (144B)
#define GTILEH (128 * GPADH)             // halves per operand-stage
#define G_SMEM (4 * GTILEH * 2)          // bytes = 73728

__global__ __launch_bounds__(128) void gemm_h(
    const __half* __restrict__ A, const __half* __restrict__ Bt,
    float* __restrict__ C, int M, int N, int K)
{
    extern __shared__ __half hsm[];
    const uint32_t sbase = smem_u32(hsm);
    const int tid = threadIdx.x;
    const int wid = tid >> 5, lane = tid & 31;
    const int g = lane >> 2, tg = lane & 3;
    const int wm = wid & 1, wn = wid >> 1;
    const int m0 = blockIdx.y * 128, n0 = blockIdx.x * 128;

    const __half* Ab = A + (size_t)m0 * K;
    const __half* Bb = Bt + (size_t)n0 * K;

    float acc[4][8][4];
    #pragma unroll
    for (int mt = 0; mt < 4; ++mt)
        #pragma unroll
        for (int nt = 0; nt < 8; ++nt)
            #pragma unroll
            for (int v = 0; v < 4; ++v) acc[mt][nt][v] = 0.f;

    const int NC = K / 64;

    auto issue_chunk = [&](int s, int k0) {
        const uint32_t abase = sbase + (uint32_t)(s * GTILEH) * 2u;
        const uint32_t bbase = sbase + (uint32_t)((2 + s) * GTILEH) * 2u;
        #pragma unroll
        for (int i = 0; i < 8; ++i) {
            const int idx = tid + 128 * i;
            const int row = idx >> 3, seg = idx & 7;
            const uint32_t d = (uint32_t)(row * 144 + seg * 16);
            cp16(abase + d, Ab + (size_t)row * K + k0 + seg * 8);
            cp16(bbase + d, Bb + (size_t)row * K + k0 + seg * 8);
        }
        asm volatile("cp.async.commit_group;" ::: "memory");
    };

    issue_chunk(0, 0);

    for (int c = 0; c < NC; ++c) {
        const int s = c & 1;
        if (c + 1 < NC) {
            issue_chunk(s ^ 1, (c + 1) * 64);
            asm volatile("cp.async.wait_group 1;" ::: "memory");
        } else {
            asm volatile("cp.async.wait_group 0;" ::: "memory");
        }
        __syncthreads();

        const __half* As = hsm + s * GTILEH;
        const __half* Bs = hsm + (2 + s) * GTILEH;
        #pragma unroll
        for (int ks = 0; ks < 4; ++ks) {
            const int k0 = ks * 16;
            uint32_t af[4][4], bf[8][2];
            #pragma unroll
            for (int mt = 0; mt < 4; ++mt) {
                const __half* p = As + (wm * 64 + mt * 16 + g) * GPADH + k0 + 2 * tg;
                af[mt][0] = *(const uint32_t*)p;
                af[mt][1] = *(const uint32_t*)(p + 8 * GPADH);
                af[mt][2] = *(const uint32_t*)(p + 8);
                af[mt][3] = *(const uint32_t*)(p + 8 * GPADH + 8);
            }
            #pragma unroll
            for (int nt = 0; nt < 8; ++nt) {
                const __half* p = Bs + (wn * 64 + nt * 8 + g) * GPADH + k0 + 2 * tg;
                bf[nt][0] = *(const uint32_t*)p;
                bf[nt][1] = *(const uint32_t*)(p + 8);
            }
            #pragma unroll
            for (int mt = 0; mt < 4; ++mt)
                #pragma unroll
                for (int nt = 0; nt < 8; ++nt)
                    mma_f16(acc[mt][nt], af[mt], bf[nt]);
        }
        __syncthreads();
    }

    #pragma unroll
    for (int mt = 0; mt < 4; ++mt) {
        const int row = m0 + wm * 64 + mt * 16 + g;
        #pragma unroll
        for (int nt = 0; nt < 8; ++nt) {
            const int col = n0 + wn * 64 + nt * 8 + 2 * tg;
            *(float2*)(C + (size_t)row * N + col) =
                make_float2(acc[mt][nt][0], acc[mt][nt][1]);
            *(float2*)(C + (size_t)(row + 8) * N + col) =
                make_float2(acc[mt][nt][2], acc[mt][nt][3]);
        }
    }
}

// ============================================================================
// RoPE + fp16 convert: Q (fp32 -> half, rotated), K half of KV (-> g_kh)
// ============================================================================
__global__ void rope_conv(const float* __restrict__ qb, const float* __restrict__ kvb,
                          __half* __restrict__ qh, __half* __restrict__ kh,
                          const float* __restrict__ cb, const float* __restrict__ sb)
{
    const int QP = NTOK * (DIMM / 2);
    const int KP = NTOK * ((NKV * HD) / 2);
    int idx = blockIdx.x * blockDim.x + threadIdx.x;
    if (idx < QP) {
        int row = idx >> 10;
        int pc  = idx & 1023;
        int i   = pc & 31;
        int n   = row & (SEQ - 1);
        float c = cb[n * 32 + i], s = sb[n * 32 + i];
        const size_t off = (size_t)row * DIMM + (pc >> 5) * HD + 2 * i;
        const float* p = qb + off;
        float xe = p[0], xo = p[1];
        *(half2*)(qh + off) = __floats2half2_rn(xe * c - xo * s, xe * s + xo * c);
    } else if (idx < QP + KP) {
        int t   = idx - QP;
        int row = t >> 8;
        int pc  = t & 255;
        int i   = pc & 31;
        int n   = row & (SEQ - 1);
        float c = cb[n * 32 + i], s = sb[n * 32 + i];
        const float* p = kvb + (size_t)row * KVC + (pc >> 5) * HD + 2 * i;
        float xe = p[0], xo = p[1];
        *(half2*)(kh + (size_t)row * (NKV * HD) + (pc >> 5) * HD + 2 * i) =
            __floats2half2_rn(xe * c - xo * s, xe * s + xo * c);
    }
}

// ============================================================================
// fp16 tensor-core causal flash attention, GQA h -> h % 8.
// CTA: 128 q x one (b,h); key tiles 64; m16n8k16; online softmax in regs.
// V pre-transposed in gmem -> coalesced staging of PV B-operand.
// ============================================================================
#define FPADH   72
#define FH_SMEM ((128 + 64 + 64) * FPADH * 2)   // 36864 B
#define QTB     (SEQ / 128)                     // 16

__global__ __launch_bounds__(256) void flash_h(
    const __half* __restrict__ qh, const __half* __restrict__ kh,
    const __half* __restrict__ vt, __half* __restrict__ oh)
{
    extern __shared__ __half fsh[];
    __half* Ps = fsh;                   // [128][FPADH] (Q staging, then P)
    __half* Ks = fsh + 128 * FPADH;     // [64][FPADH]  rows = keys
    __half* Vs = Ks + 64 * FPADH;       // [64][FPADH]  rows = dims (V^T)

    const int qtb = (QTB - 1) - blockIdx.x;
    const int h = blockIdx.y, b = blockIdx.z;
    const int kvh = h & (NKV - 1);
    const int bk = b * NKV + kvh;
    const int tid = threadIdx.x;
    const int wid = tid >> 5, lane = tid & 31;
    const int g = lane >> 2, tg = lane & 3;
    const int wrow = wid * 16;
    const int q0 = qtb * 128;

    // ---- stage Q (half, unscaled) ----
    #pragma unroll
    for (int i = 0; i < 4; ++i) {
        int idx = tid + i * 256;           // 0..1023
        int row = idx >> 3, seg = idx & 7;
        *(uint4*)&Ps[row * FPADH + seg * 8] =
            *(const uint4*)&qh[(size_t)(b * SEQ + q0 + row) * DIMM + h * HD + seg * 8];
    }
    __syncthreads();

    // ---- Q fragments: 4 k-steps x 4 regs ----
    uint32_t qf[4][4];
    #pragma unroll
    for (int ks = 0; ks < 4; ++ks) {
        const __half* p = Ps + (wrow + g) * FPADH + ks * 16 + 2 * tg;
        qf[ks][0] = *(const uint32_t*)p;
        qf[ks][1] = *(const uint32_t*)(p + 8 * FPADH);
        qf[ks][2] = *(const uint32_t*)(p + 8);
        qf[ks][3] = *(const uint32_t*)(p + 8 * FPADH + 8);
    }

    float m_g = -1e30f, m_g8 = -1e30f, l_g = 0.f, l_g8 = 0.f;
    float acc[8][4];
    #pragma unroll
    for (int nt = 0; nt < 8; ++nt)
        #pragma unroll
        for (int v = 0; v < 4; ++v) acc[nt][v] = 0.f;

    const int ktmax = 2 * qtb + 1;

    // prologue: load tile 0 into regs
    uint4 kr[2], vr[2];
    #pragma unroll
    for (int i = 0; i < 2; ++i) {
        int idx = tid + i * 256;           // 0..511
        int r = idx >> 3, seg = idx & 7;
        kr[i] = *(const uint4*)&kh[(size_t)(b * SEQ + r) * (NKV * HD) + kvh * HD + seg * 8];
        vr[i] = *(const uint4*)&vt[((size_t)bk * HD + r) * SEQ + seg * 8];
    }

    for (int kt = 0; kt <= ktmax; ++kt) {
        __syncthreads();
        #pragma unroll
        for (int i = 0; i < 2; ++i) {
            int idx = tid + i * 256;
            int r = idx >> 3, seg = idx & 7;
            *(uint4*)&Ks[r * FPADH + seg * 8] = kr[i];
            *(uint4*)&Vs[r * FPADH + seg * 8] = vr[i];
        }
        __syncthreads();

        if (kt < ktmax) {
            #pragma unroll
            for (int i = 0; i < 2; ++i) {
                int idx = tid + i * 256;
                int r = idx >> 3, seg = idx & 7;
                kr[i] = *(const uint4*)&kh[(size_t)(b * SEQ + (kt + 1) * 64 + r) * (NKV * HD) + kvh * HD + seg * 8];
                vr[i] = *(const uint4*)&vt[((size_t)bk * HD + r) * SEQ + (kt + 1) * 64 + seg * 8];
            }
        }

        // ---- S = Q @ K^T ----
        float sA[8][4];
        #pragma unroll
        for (int nt = 0; nt < 8; ++nt)
            #pragma unroll
            for (int v = 0; v < 4; ++v) sA[nt][v] = 0.f;
        #pragma unroll
        for (int ks = 0; ks < 4; ++ks) {
            uint32_t bf[8][2];
            #pragma unroll
            for (int nt = 0; nt < 8; ++nt) {
                const __half* p = Ks + (nt * 8 + g) * FPADH + ks * 16 + 2 * tg;
                bf[nt][0] = *(const uint32_t*)p;
                bf[nt][1] = *(const uint32_t*)(p + 8);
            }
            #pragma unroll
            for (int nt = 0; nt < 8; ++nt)
                mma_f16(sA[nt], qf[ks], bf[nt]);
        }
        // scale logits
        #pragma unroll
        for (int nt = 0; nt < 8; ++nt) {
            sA[nt][0] *= 0.125f; sA[nt][1] *= 0.125f;
            sA[nt][2] *= 0.125f; sA[nt][3] *= 0.125f;
        }

        // ---- causal mask (diagonal tiles) ----
        if (kt >= 2 * qtb) {
            const int qr = q0 + wrow + g;
            const int kc0 = kt * 64;
            #pragma unroll
            for (int nt = 0; nt < 8; ++nt) {
                const int col = kc0 + nt * 8 + 2 * tg;
                if (col > qr)         sA[nt][0] = -1e30f;
                if (col + 1 > qr)     sA[nt][1] = -1e30f;
                if (col > qr + 8)     sA[nt][2] = -1e30f;
                if (col + 1 > qr + 8) sA[nt][3] = -1e30f;
            }
        }

        // ---- online softmax in registers ----
        float mxg = -1e30f, mxg8 = -1e30f;
        #pragma unroll
        for (int nt = 0; nt < 8; ++nt) {
            mxg  = fmaxf(mxg,  fmaxf(sA[nt][0], sA[nt][1]));
            mxg8 = fmaxf(mxg8, fmaxf(sA[nt][2], sA[nt][3]));
        }
        mxg  = fmaxf(mxg,  __shfl_xor_sync(0xffffffffu, mxg, 1));
        mxg  = fmaxf(mxg,  __shfl_xor_sync(0xffffffffu, mxg, 2));
        mxg8 = fmaxf(mxg8, __shfl_xor_sync(0xffffffffu, mxg8, 1));
        mxg8 = fmaxf(mxg8, __shfl_xor_sync(0xffffffffu, mxg8, 2));

        const float mn_g  = fmaxf(m_g,  mxg);
        const float mn_g8 = fmaxf(m_g8, mxg8);
        const float cr_g  = __expf(m_g  - mn_g);
        const float cr_g8 = __expf(m_g8 - mn_g8);

        float sum_g = 0.f, sum_g8 = 0.f;
        #pragma unroll
        for (int nt = 0; nt < 8; ++nt) {
            sA[nt][0] = __expf(sA[nt][0] - mn_g);
            sA[nt][1] = __expf(sA[nt][1] - mn_g);
            sA[nt][2] = __expf(sA[nt][2] - mn_g8);
            sA[nt][3] = __expf(sA[nt][3] - mn_g8);
            sum_g  += sA[nt][0] + sA[nt][1];
            sum_g8 += sA[nt][2] + sA[nt][3];
        }
        sum_g  += __shfl_xor_sync(0xffffffffu, sum_g, 1);
        sum_g  += __shfl_xor_sync(0xffffffffu, sum_g, 2);
        sum_g8 += __shfl_xor_sync(0xffffffffu, sum_g8, 1);
        sum_g8 += __shfl_xor_sync(0xffffffffu, sum_g8, 2);

        m_g = mn_g;  l_g  = l_g  * cr_g  + sum_g;
        m_g8 = mn_g8; l_g8 = l_g8 * cr_g8 + sum_g8;

        // ---- P -> smem (half); per-warp-private rows ----
        {
            __half* pr = Ps + (wrow + g) * FPADH;
            #pragma unroll
            for (int nt = 0; nt < 8; ++nt) {
                *(half2*)(pr + nt * 8 + 2 * tg) = __floats2half2_rn(sA[nt][0], sA[nt][1]);
                *(half2*)(pr + 8 * FPADH + nt * 8 + 2 * tg) = __floats2half2_rn(sA[nt][2], sA[nt][3]);
            }
        }
        __syncwarp();

        // ---- rescale acc ----
        #pragma unroll
        for (int nt = 0; nt < 8; ++nt) {
            acc[nt][0] *= cr_g;  acc[nt][1] *= cr_g;
            acc[nt][2] *= cr_g8; acc[nt][3] *= cr_g8;
        }

        // ---- O += P @ V ----
        #pragma unroll
        for (int ks = 0; ks < 4; ++ks) {
            uint32_t af[4];
            {
                const __half* p = Ps + (wrow + g) * FPADH + ks * 16 + 2 * tg;
                af[0] = *(const uint32_t*)p;
                af[1] = *(const uint32_t*)(p + 8 * FPADH);
                af[2] = *(const uint32_t*)(p + 8);
                af[3] = *(const uint32_t*)(p + 8 * FPADH + 8);
            }
            uint32_t bf[8][2];
            #pragma unroll
            for (int nt = 0; nt < 8; ++nt) {
                const __half* p = Vs + (nt * 8 + g) * FPADH + ks * 16 + 2 * tg;
                bf[nt][0] = *(const uint32_t*)p;
                bf[nt][1] = *(const uint32_t*)(p + 8);
            }
            #pragma unroll
            for (int nt = 0; nt < 8; ++nt)
                mma_f16(acc[nt], af, bf[nt]);
        }
    }

    // ---- epilogue: normalize, write half att ----
    const float il_g = 1.f / l_g, il_g8 = 1.f / l_g8;
    __half* ob  = oh + (size_t)(b * SEQ + q0 + wrow + g) * DIMM + h * HD;
    __half* ob8 = ob + 8 * DIMM;
    #pragma unroll
    for (int nt = 0; nt < 8; ++nt) {
        const int col = nt * 8 + 2 * tg;
        *(half2*)(ob + col)  = __floats2half2_rn(acc[nt][0] * il_g,  acc[nt][1] * il_g);
        *(half2*)(ob8 + col) = __floats2half2_rn(acc[nt][2] * il_g8, acc[nt][3] * il_g8);
    }
}

// ============================================================================
extern "C" void kernel_launch(void* const* d_in, const int* in_sizes, int n_in,
                              void* d_out, int out_size)
{
    const float* x   = (const float*)d_in[0];
    const float* Wq  = (const float*)d_in[1];
    const float* Wkv = (const float*)d_in[2];
    const float* Wo  = (const float*)d_in[3];
    const float* cb  = (const float*)d_in[4];
    const float* sb  = (const float*)d_in[5];
    float* out = (float*)d_out;

    __half *xh, *qhp, *khp, *vtp, *ahp, *wqt, *wkvt, *wot;
    float *qb, *kvb;
    cudaGetSymbolAddress((void**)&xh,   g_xh);
    cudaGetSymbolAddress((void**)&qb,   g_q);
    cudaGetSymbolAddress((void**)&kvb,  g_kv);
    cudaGetSymbolAddress((void**)&qhp,  g_qh);
    cudaGetSymbolAddress((void**)&khp,  g_kh);
    cudaGetSymbolAddress((void**)&vtp,  g_vt);
    cudaGetSymbolAddress((void**)&ahp,  g_ah);
    cudaGetSymbolAddress((void**)&wqt,  g_wqt);
    cudaGetSymbolAddress((void**)&wkvt, g_wkvt);
    cudaGetSymbolAddress((void**)&wot,  g_wot);

    cudaFuncSetAttribute(gemm_h,
                         cudaFuncAttributeMaxDynamicSharedMemorySize, G_SMEM);
    cudaFuncSetAttribute(flash_h,
                         cudaFuncAttributeMaxDynamicSharedMemorySize, FH_SMEM);

    // convert x; transpose + convert weights
    {
        int n2 = NTOK * DIMM / 2;
        conv_x<<<(n2 + 255) / 256, 256>>>(x, xh, n2);
    }
    transpose32h<<<dim3(DIMM / 32, DIMM / 32), dim3(32, 8)>>>(Wq, wqt, DIMM, DIMM);
    transpose32h<<<dim3(KVC / 32, DIMM / 32), dim3(32, 8)>>>(Wkv, wkvt, DIMM, KVC);
    transpose32h<<<dim3(DIMM / 32, DIMM / 32), dim3(32, 8)>>>(Wo, wot, DIMM, DIMM);

    // Q = x @ Wq ; KV = x @ Wkv  (fp32 out)
    gemm_h<<<dim3(DIMM / 128, NTOK / 128), 128, G_SMEM>>>(xh, wqt, qb, NTOK, DIMM, DIMM);
    gemm_h<<<dim3(KVC / 128, NTOK / 128), 128, G_SMEM>>>(xh, wkvt, kvb, NTOK, KVC, DIMM);

    // RoPE(Q,K) -> half; V -> transposed half
    {
        int totalPairs = NTOK * (DIMM / 2) + NTOK * ((NKV * HD) / 2);
        rope_conv<<<(totalPairs + 255) / 256, 256>>>(qb, kvb, qhp, khp, cb, sb);
    }
    transposeV<<<dim3(SEQ / 32, HD / 32, BATCH * NKV), dim3(32, 8)>>>(kvb, vtp);

    // fp16 tensor-core causal GQA flash attention
    flash_h<<<dim3(QTB, NH, BATCH), 256, FH_SMEM>>>(qhp, khp, vtp, ahp);

    // out = att @ Wo (fp32 out)
    gemm_h<<<dim3(DIMM / 128, NTOK / 128), 128, G_SMEM>>>(ahp, wot, out, NTOK, DIMM, DIMM);
}

// round 7
// speedup vs baseline: 10.5352x; 1.0879x over previous
#include <cuda_runtime.h>
#include <cuda_fp16.h>
#include <cstdint>

#define SEQ   2048
#define BATCH 2
#define NTOK  (SEQ * BATCH)      // 4096
#define DIMM  2048
#define NH    32
#define NKV   8
#define HD    64
#define KVC   (2 * NKV * HD)     // 1024

// ---- scratch (static device globals: allocation-free) ----
__device__ __half g_xh[(size_t)NTOK * DIMM];
__device__ __half g_qh[(size_t)NTOK * DIMM];            // Q after rope (half)
__device__ __half g_kh[(size_t)NTOK * NKV * HD];        // K after rope (half)
__device__ __half g_vt[(size_t)BATCH * NKV * HD * SEQ]; // V^T [b][kvh][d][n]
__device__ __half g_ah[(size_t)NTOK * DIMM];            // attention out (half)
__device__ __half g_wqt[(size_t)DIMM * DIMM];
__device__ __half g_wkvt[(size_t)KVC * DIMM];
__device__ __half g_wot[(size_t)DIMM * DIMM];

__device__ __forceinline__ uint32_t smem_u32(const void* p) {
    uint32_t a;
    asm("{ .reg .u64 t; cvta.to.shared.u64 t, %1; cvt.u32.u64 %0, t; }" : "=r"(a) : "l"(p));
    return a;
}
__device__ __forceinline__ void mma_f16(float* d, const uint32_t* a, const uint32_t* b) {
    asm volatile(
        "mma.sync.aligned.m16n8k16.row.col.f32.f16.f16.f32 "
        "{%0,%1,%2,%3}, {%4,%5,%6,%7}, {%8,%9}, {%0,%1,%2,%3};"
        : "+f"(d[0]), "+f"(d[1]), "+f"(d[2]), "+f"(d[3])
        : "r"(a[0]), "r"(a[1]), "r"(a[2]), "r"(a[3]), "r"(b[0]), "r"(b[1]));
}
__device__ __forceinline__ void ldsm4(uint32_t* r, uint32_t addr) {
    asm volatile("ldmatrix.sync.aligned.m8n8.x4.shared.b16 {%0,%1,%2,%3}, [%4];"
        : "=r"(r[0]), "=r"(r[1]), "=r"(r[2]), "=r"(r[3]) : "r"(addr));
}
__device__ __forceinline__ void cp16(uint32_t dst, const void* src) {
    asm volatile("cp.async.cg.shared.global [%0], [%1], 16;" :: "r"(dst), "l"(src));
}

// ============================================================================
// x: fp32 -> fp16
// ============================================================================
__global__ void conv_x(const float* __restrict__ in, __half* __restrict__ out, int n2)
{
    int i = blockIdx.x * blockDim.x + threadIdx.x;
    if (i < n2) {
        float2 t = ((const float2*)in)[i];
        ((half2*)out)[i] = __floats2half2_rn(t.x, t.y);
    }
}

// ============================================================================
// Weight transpose fp32 -> fp16
// ============================================================================
__global__ void transpose32h(const float* __restrict__ in, __half* __restrict__ out,
                             int R, int C)
{
    __shared__ float t[32][33];
    const int bc = blockIdx.x * 32, br = blockIdx.y * 32;
    const int tx = threadIdx.x;
    for (int i = threadIdx.y; i < 32; i += 8)
        t[i][tx] = in[(size_t)(br + i) * C + bc + tx];
    __syncthreads();
    for (int i = threadIdx.y; i < 32; i += 8)
        out[(size_t)(bc + i) * R + br + tx] = __float2half_rn(t[tx][i]);
}

// ============================================================================
// fp16 mma.sync GEMM with fused epilogues.
// mode 0: fp32 out (O-proj).  mode 1: rope -> half (Q).
// mode 2: cols<512 rope -> kh; cols>=512 -> transposed half scatter to vt (V).
// 128 threads (4 warps, 2M x 2N), CTA 128x128, warp 64x64, BK=64, ldmatrix.
// ============================================================================
#define GPADH  72                        // halves per padded smem row (144B)
#define GTILEH (128 * GPADH)
#define G_SMEM (4 * GTILEH * 2)          // 73728 B

__global__ __launch_bounds__(128) void gemm_h(
    const __half* __restrict__ A, const __half* __restrict__ Bt,
    float* __restrict__ Cf, __half* __restrict__ Ch, __half* __restrict__ vt,
    const float* __restrict__ cb, const float* __restrict__ sb,
    int M, int N, int K, int mode)
{
    extern __shared__ __half hsm[];
    const uint32_t sbase = smem_u32(hsm);
    const int tid = threadIdx.x;
    const int wid = tid >> 5, lane = tid & 31;
    const int g = lane >> 2, tg = lane & 3;
    const int wm = wid & 1, wn = wid >> 1;
    const int m0 = blockIdx.y * 128, n0 = blockIdx.x * 128;

    // ldmatrix per-lane address components
    const int arow  = (lane & 7) + ((lane >> 3) & 1) * 8;
    const int akoff = (lane >> 4) * 8;
    const int brow  = (lane & 7) + ((lane >> 4) & 1) * 8;
    const int bkoff = ((lane >> 3) & 1) * 8;

    const __half* Ab = A + (size_t)m0 * K;
    const __half* Bb = Bt + (size_t)n0 * K;

    float acc[4][8][4];
    #pragma unroll
    for (int mt = 0; mt < 4; ++mt)
        #pragma unroll
        for (int nt = 0; nt < 8; ++nt)
            #pragma unroll
            for (int v = 0; v < 4; ++v) acc[mt][nt][v] = 0.f;

    const int NC = K / 64;

    auto issue_chunk = [&](int s, int k0) {
        const uint32_t abase = sbase + (uint32_t)(s * GTILEH) * 2u;
        const uint32_t bbase = sbase + (uint32_t)((2 + s) * GTILEH) * 2u;
        #pragma unroll
        for (int i = 0; i < 8; ++i) {
            const int idx = tid + 128 * i;
            const int row = idx >> 3, seg = idx & 7;
            const uint32_t d = (uint32_t)(row * 144 + seg * 16);
            cp16(abase + d, Ab + (size_t)row * K + k0 + seg * 8);
            cp16(bbase + d, Bb + (size_t)row * K + k0 + seg * 8);
        }
        asm volatile("cp.async.commit_group;" ::: "memory");
    };

    issue_chunk(0, 0);

    for (int c = 0; c < NC; ++c) {
        const int s = c & 1;
        if (c + 1 < NC) {
            issue_chunk(s ^ 1, (c + 1) * 64);
            asm volatile("cp.async.wait_group 1;" ::: "memory");
        } else {
            asm volatile("cp.async.wait_group 0;" ::: "memory");
        }
        __syncthreads();

        const uint32_t As = sbase + (uint32_t)(s * GTILEH) * 2u;
        const uint32_t Bs = sbase + (uint32_t)((2 + s) * GTILEH) * 2u;
        #pragma unroll
        for (int ks = 0; ks < 4; ++ks) {
            const int k0 = ks * 16;
            uint32_t af[4][4];
            #pragma unroll
            for (int mt = 0; mt < 4; ++mt)
                ldsm4(af[mt], As + (uint32_t)((wm * 64 + mt * 16 + arow) * GPADH + k0 + akoff) * 2u);
            #pragma unroll
            for (int ntp = 0; ntp < 4; ++ntp) {
                uint32_t t4[4];
                ldsm4(t4, Bs + (uint32_t)((wn * 64 + ntp * 16 + brow) * GPADH + k0 + bkoff) * 2u);
                #pragma unroll
                for (int mt = 0; mt < 4; ++mt) {
                    mma_f16(acc[mt][2 * ntp],     af[mt], t4);
                    mma_f16(acc[mt][2 * ntp + 1], af[mt], t4 + 2);
                }
            }
        }
        __syncthreads();
    }

    // ---- epilogues ----
    if (mode == 0) {
        #pragma unroll
        for (int mt = 0; mt < 4; ++mt) {
            const int row = m0 + wm * 64 + mt * 16 + g;
            #pragma unroll
            for (int nt = 0; nt < 8; ++nt) {
                const int col = n0 + wn * 64 + nt * 8 + 2 * tg;
                *(float2*)(Cf + (size_t)row * N + col) =
                    make_float2(acc[mt][nt][0], acc[mt][nt][1]);
                *(float2*)(Cf + (size_t)(row + 8) * N + col) =
                    make_float2(acc[mt][nt][2], acc[mt][nt][3]);
            }
        }
    } else if (mode == 1) {
        #pragma unroll
        for (int mt = 0; mt < 4; ++mt) {
            const int row = m0 + wm * 64 + mt * 16 + g;
            const int n1 = row & (SEQ - 1), n2 = (row + 8) & (SEQ - 1);
            #pragma unroll
            for (int nt = 0; nt < 8; ++nt) {
                const int col = n0 + wn * 64 + nt * 8 + 2 * tg;
                const int fi = (col & 63) >> 1;
                float c1 = cb[n1 * 32 + fi], s1 = sb[n1 * 32 + fi];
                float c2 = cb[n2 * 32 + fi], s2 = sb[n2 * 32 + fi];
                *(half2*)(Ch + (size_t)row * N + col) = __floats2half2_rn(
                    acc[mt][nt][0] * c1 - acc[mt][nt][1] * s1,
                    acc[mt][nt][0] * s1 + acc[mt][nt][1] * c1);
                *(half2*)(Ch + (size_t)(row + 8) * N + col) = __floats2half2_rn(
                    acc[mt][nt][2] * c2 - acc[mt][nt][3] * s2,
                    acc[mt][nt][2] * s2 + acc[mt][nt][3] * c2);
            }
        }
    } else {
        #pragma unroll
        for (int mt = 0; mt < 4; ++mt) {
            const int row = m0 + wm * 64 + mt * 16 + g;
            const int n1 = row & (SEQ - 1), n2 = (row + 8) & (SEQ - 1);
            const int b_ = row >> 11;
            #pragma unroll
            for (int nt = 0; nt < 8; ++nt) {
                const int col = n0 + wn * 64 + nt * 8 + 2 * tg;
                if (col < 512) {   // K half: rope -> kh  (warp-uniform branch)
                    const int fi = (col & 63) >> 1;
                    float c1 = cb[n1 * 32 + fi], s1 = sb[n1 * 32 + fi];
                    float c2 = cb[n2 * 32 + fi], s2 = sb[n2 * 32 + fi];
                    *(half2*)(Ch + (size_t)row * 512 + col) = __floats2half2_rn(
                        acc[mt][nt][0] * c1 - acc[mt][nt][1] * s1,
                        acc[mt][nt][0] * s1 + acc[mt][nt][1] * c1);
                    *(half2*)(Ch + (size_t)(row + 8) * 512 + col) = __floats2half2_rn(
                        acc[mt][nt][2] * c2 - acc[mt][nt][3] * s2,
                        acc[mt][nt][2] * s2 + acc[mt][nt][3] * c2);
                } else {           // V half: transposed scatter -> vt
                    const int cm = col - 512;
                    const int kvh = cm >> 6, d = cm & 63;
                    __half* vb = vt + ((size_t)((b_ * NKV + kvh) * HD + d)) * SEQ;
                    vb[n1]       = __float2half_rn(acc[mt][nt][0]);
                    vb[SEQ + n1] = __float2half_rn(acc[mt][nt][1]);
                    vb[n2]       = __float2half_rn(acc[mt][nt][2]);
                    vb[SEQ + n2] = __float2half_rn(acc[mt][nt][3]);
                }
            }
        }
    }
}

// ============================================================================
// fp16 tensor-core causal flash attention, GQA h -> h % 8, ldmatrix fragments.
// ============================================================================
#define FPADH   72
#define FH_SMEM ((128 + 64 + 64) * FPADH * 2)   // 36864 B
#define QTB     (SEQ / 128)                     // 16

__global__ __launch_bounds__(256) void flash_h(
    const __half* __restrict__ qh, const __half* __restrict__ kh,
    const __half* __restrict__ vt, __half* __restrict__ oh)
{
    extern __shared__ __half fsh[];
    __half* Ps = fsh;                   // [128][FPADH]
    __half* Ks = fsh + 128 * FPADH;     // [64][FPADH] rows = keys
    __half* Vs = Ks + 64 * FPADH;       // [64][FPADH] rows = dims (V^T)
    const uint32_t Pu = smem_u32(Ps);
    const uint32_t Ku = smem_u32(Ks);
    const uint32_t Vu = smem_u32(Vs);

    const int qtb = (QTB - 1) - blockIdx.x;
    const int h = blockIdx.y, b = blockIdx.z;
    const int kvh = h & (NKV - 1);
    const int bk = b * NKV + kvh;
    const int tid = threadIdx.x;
    const int wid = tid >> 5, lane = tid & 31;
    const int g = lane >> 2, tg = lane & 3;
    const int wrow = wid * 16;
    const int q0 = qtb * 128;

    const int arow  = (lane & 7) + ((lane >> 3) & 1) * 8;
    const int akoff = (lane >> 4) * 8;
    const int brow  = (lane & 7) + ((lane >> 4) & 1) * 8;
    const int bkoff = ((lane >> 3) & 1) * 8;

    // ---- stage Q ----
    #pragma unroll
    for (int i = 0; i < 4; ++i) {
        int idx = tid + i * 256;
        int row = idx >> 3, seg = idx & 7;
        *(uint4*)&Ps[row * FPADH + seg * 8] =
            *(const uint4*)&qh[(size_t)(b * SEQ + q0 + row) * DIMM + h * HD + seg * 8];
    }
    __syncthreads();

    // ---- Q fragments via ldmatrix ----
    uint32_t qf[4][4];
    #pragma unroll
    for (int ks = 0; ks < 4; ++ks)
        ldsm4(qf[ks], Pu + (uint32_t)((wrow + arow) * FPADH + ks * 16 + akoff) * 2u);

    float m_g = -1e30f, m_g8 = -1e30f, l_g = 0.f, l_g8 = 0.f;
    float acc[8][4];
    #pragma unroll
    for (int nt = 0; nt < 8; ++nt)
        #pragma unroll
        for (int v = 0; v < 4; ++v) acc[nt][v] = 0.f;

    const int ktmax = 2 * qtb + 1;

    uint4 kr[2], vr[2];
    #pragma unroll
    for (int i = 0; i < 2; ++i) {
        int idx = tid + i * 256;
        int r = idx >> 3, seg = idx & 7;
        kr[i] = *(const uint4*)&kh[(size_t)(b * SEQ + r) * (NKV * HD) + kvh * HD + seg * 8];
        vr[i] = *(const uint4*)&vt[((size_t)bk * HD + r) * SEQ + seg * 8];
    }

    for (int kt = 0; kt <= ktmax; ++kt) {
        __syncthreads();
        #pragma unroll
        for (int i = 0; i < 2; ++i) {
            int idx = tid + i * 256;
            int r = idx >> 3, seg = idx & 7;
            *(uint4*)&Ks[r * FPADH + seg * 8] = kr[i];
            *(uint4*)&Vs[r * FPADH + seg * 8] = vr[i];
        }
        __syncthreads();

        if (kt < ktmax) {
            #pragma unroll
            for (int i = 0; i < 2; ++i) {
                int idx = tid + i * 256;
                int r = idx >> 3, seg = idx & 7;
                kr[i] = *(const uint4*)&kh[(size_t)(b * SEQ + (kt + 1) * 64 + r) * (NKV * HD) + kvh * HD + seg * 8];
                vr[i] = *(const uint4*)&vt[((size_t)bk * HD + r) * SEQ + (kt + 1) * 64 + seg * 8];
            }
        }

        // ---- S = Q @ K^T ----
        float sA[8][4];
        #pragma unroll
        for (int nt = 0; nt < 8; ++nt)
            #pragma unroll
            for (int v = 0; v < 4; ++v) sA[nt][v] = 0.f;
        #pragma unroll
        for (int ks = 0; ks < 4; ++ks) {
            #pragma unroll
            for (int ntp = 0; ntp < 4; ++ntp) {
                uint32_t t4[4];
                ldsm4(t4, Ku + (uint32_t)((ntp * 16 + brow) * FPADH + ks * 16 + bkoff) * 2u);
                mma_f16(sA[2 * ntp],     qf[ks], t4);
                mma_f16(sA[2 * ntp + 1], qf[ks], t4 + 2);
            }
        }
        #pragma unroll
        for (int nt = 0; nt < 8; ++nt) {
            sA[nt][0] *= 0.125f; sA[nt][1] *= 0.125f;
            sA[nt][2] *= 0.125f; sA[nt][3] *= 0.125f;
        }

        // ---- causal mask ----
        if (kt >= 2 * qtb) {
            const int qr = q0 + wrow + g;
            const int kc0 = kt * 64;
            #pragma unroll
            for (int nt = 0; nt < 8; ++nt) {
                const int col = kc0 + nt * 8 + 2 * tg;
                if (col > qr)         sA[nt][0] = -1e30f;
                if (col + 1 > qr)     sA[nt][1] = -1e30f;
                if (col > qr + 8)     sA[nt][2] = -1e30f;
                if (col + 1 > qr + 8) sA[nt][3] = -1e30f;
            }
        }

        // ---- online softmax in registers ----
        float mxg = -1e30f, mxg8 = -1e30f;
        #pragma unroll
        for (int nt = 0; nt < 8; ++nt) {
            mxg  = fmaxf(mxg,  fmaxf(sA[nt][0], sA[nt][1]));
            mxg8 = fmaxf(mxg8, fmaxf(sA[nt][2], sA[nt][3]));
        }
        mxg  = fmaxf(mxg,  __shfl_xor_sync(0xffffffffu, mxg, 1));
        mxg  = fmaxf(mxg,  __shfl_xor_sync(0xffffffffu, mxg, 2));
        mxg8 = fmaxf(mxg8, __shfl_xor_sync(0xffffffffu, mxg8, 1));
        mxg8 = fmaxf(mxg8, __shfl_xor_sync(0xffffffffu, mxg8, 2));

        const float mn_g  = fmaxf(m_g,  mxg);
        const float mn_g8 = fmaxf(m_g8, mxg8);
        const float cr_g  = __expf(m_g  - mn_g);
        const float cr_g8 = __expf(m_g8 - mn_g8);

        float sum_g = 0.f, sum_g8 = 0.f;
        #pragma unroll
        for (int nt = 0; nt < 8; ++nt) {
            sA[nt][0] = __expf(sA[nt][0] - mn_g);
            sA[nt][1] = __expf(sA[nt][1] - mn_g);
            sA[nt][2] = __expf(sA[nt][2] - mn_g8);
            sA[nt][3] = __expf(sA[nt][3] - mn_g8);
            sum_g  += sA[nt][0] + sA[nt][1];
            sum_g8 += sA[nt][2] + sA[nt][3];
        }
        sum_g  += __shfl_xor_sync(0xffffffffu, sum_g, 1);
        sum_g  += __shfl_xor_sync(0xffffffffu, sum_g, 2);
        sum_g8 += __shfl_xor_sync(0xffffffffu, sum_g8, 1);
        sum_g8 += __shfl_xor_sync(0xffffffffu, sum_g8, 2);

        m_g = mn_g;  l_g  = l_g  * cr_g  + sum_g;
        m_g8 = mn_g8; l_g8 = l_g8 * cr_g8 + sum_g8;

        // ---- P -> smem (half); per-warp-private rows ----
        {
            __half* pr = Ps + (wrow + g) * FPADH;
            #pragma unroll
            for (int nt = 0; nt < 8; ++nt) {
                *(half2*)(pr + nt * 8 + 2 * tg) = __floats2half2_rn(sA[nt][0], sA[nt][1]);
                *(half2*)(pr + 8 * FPADH + nt * 8 + 2 * tg) = __floats2half2_rn(sA[nt][2], sA[nt][3]);
            }
        }
        __syncwarp();

        // ---- rescale acc ----
        #pragma unroll
        for (int nt = 0; nt < 8; ++nt) {
            acc[nt][0] *= cr_g;  acc[nt][1] *= cr_g;
            acc[nt][2] *= cr_g8; acc[nt][3] *= cr_g8;
        }

        // ---- O += P @ V ----
        #pragma unroll
        for (int ks = 0; ks < 4; ++ks) {
            uint32_t af[4];
            ldsm4(af, Pu + (uint32_t)((wrow + arow) * FPADH + ks * 16 + akoff) * 2u);
            #pragma unroll
            for (int ntp = 0; ntp < 4; ++ntp) {
                uint32_t t4[4];
                ldsm4(t4, Vu + (uint32_t)((ntp * 16 + brow) * FPADH + ks * 16 + bkoff) * 2u);
                mma_f16(acc[2 * ntp],     af, t4);
                mma_f16(acc[2 * ntp + 1], af, t4 + 2);
            }
        }
    }

    // ---- epilogue ----
    const float il_g = 1.f / l_g, il_g8 = 1.f / l_g8;
    __half* ob  = oh + (size_t)(b * SEQ + q0 + wrow + g) * DIMM + h * HD;
    __half* ob8 = ob + 8 * DIMM;
    #pragma unroll
    for (int nt = 0; nt < 8; ++nt) {
        const int col = nt * 8 + 2 * tg;
        *(half2*)(ob + col)  = __floats2half2_rn(acc[nt][0] * il_g,  acc[nt][1] * il_g);
        *(half2*)(ob8 + col) = __floats2half2_rn(acc[nt][2] * il_g8, acc[nt][3] * il_g8);
    }
}

// ============================================================================
extern "C" void kernel_launch(void* const* d_in, const int* in_sizes, int n_in,
                              void* d_out, int out_size)
{
    const float* x   = (const float*)d_in[0];
    const float* Wq  = (const float*)d_in[1];
    const float* Wkv = (const float*)d_in[2];
    const float* Wo  = (const float*)d_in[3];
    const float* cb  = (const float*)d_in[4];
    const float* sb  = (const float*)d_in[5];
    float* out = (float*)d_out;

    __half *xh, *qhp, *khp, *vtp, *ahp, *wqt, *wkvt, *wot;
    cudaGetSymbolAddress((void**)&xh,   g_xh);
    cudaGetSymbolAddress((void**)&qhp,  g_qh);
    cudaGetSymbolAddress((void**)&khp,  g_kh);
    cudaGetSymbolAddress((void**)&vtp,  g_vt);
    cudaGetSymbolAddress((void**)&ahp,  g_ah);
    cudaGetSymbolAddress((void**)&wqt,  g_wqt);
    cudaGetSymbolAddress((void**)&wkvt, g_wkvt);
    cudaGetSymbolAddress((void**)&wot,  g_wot);

    cudaFuncSetAttribute(gemm_h,
                         cudaFuncAttributeMaxDynamicSharedMemorySize, G_SMEM);
    cudaFuncSetAttribute(flash_h,
                         cudaFuncAttributeMaxDynamicSharedMemorySize, FH_SMEM);

    {
        int n2 = NTOK * DIMM / 2;
        conv_x<<<(n2 + 255) / 256, 256>>>(x, xh, n2);
    }
    transpose32h<<<dim3(DIMM / 32, DIMM / 32), dim3(32, 8)>>>(Wq, wqt, DIMM, DIMM);
    transpose32h<<<dim3(KVC / 32, DIMM / 32), dim3(32, 8)>>>(Wkv, wkvt, DIMM, KVC);
    transpose32h<<<dim3(DIMM / 32, DIMM / 32), dim3(32, 8)>>>(Wo, wot, DIMM, DIMM);

    // Q = rope(x @ Wq) -> half   (fused epilogue)
    gemm_h<<<dim3(DIMM / 128, NTOK / 128), 128, G_SMEM>>>(
        xh, wqt, nullptr, qhp, nullptr, cb, sb, NTOK, DIMM, DIMM, 1);
    // KV = x @ Wkv: K rope -> kh, V -> transposed vt   (fused epilogue)
    gemm_h<<<dim3(KVC / 128, NTOK / 128), 128, G_SMEM>>>(
        xh, wkvt, nullptr, khp, vtp, cb, sb, NTOK, KVC, DIMM, 2);

    // fp16 tensor-core causal GQA flash attention
    flash_h<<<dim3(QTB, NH, BATCH), 256, FH_SMEM>>>(qhp, khp, vtp, ahp);

    // out = att @ Wo (fp32 out)
    gemm_h<<<dim3(DIMM / 128, NTOK / 128), 128, G_SMEM>>>(
        ahp, wot, out, nullptr, nullptr, nullptr, nullptr, NTOK, DIMM, DIMM, 0);
}

// round 8
// speedup vs baseline: 10.9786x; 1.0421x over previous
#include <cuda_runtime.h>
#include <cuda_fp16.h>
#include <cstdint>

#define SEQ   2048
#define BATCH 2
#define NTOK  (SEQ * BATCH)      // 4096
#define DIMM  2048
#define NH    32
#define NKV   8
#define HD    64
#define KVC   (2 * NKV * HD)     // 1024

// ---- scratch (static device globals: allocation-free) ----
__device__ __half g_xh[(size_t)NTOK * DIMM];
__device__ __half g_qh[(size_t)NTOK * DIMM];            // Q after rope (half)
__device__ __half g_kh[(size_t)NTOK * NKV * HD];        // K after rope (half)
__device__ __half g_vt[(size_t)BATCH * NKV * HD * SEQ]; // V^T [b][kvh][d][n]
__device__ __half g_ah[(size_t)NTOK * DIMM];            // attention out (half)

__device__ __forceinline__ uint32_t smem_u32(const void* p) {
    uint32_t a;
    asm("{ .reg .u64 t; cvta.to.shared.u64 t, %1; cvt.u32.u64 %0, t; }" : "=r"(a) : "l"(p));
    return a;
}
__device__ __forceinline__ void mma_f16(float* d, const uint32_t* a, const uint32_t* b) {
    asm volatile(
        "mma.sync.aligned.m16n8k16.row.col.f32.f16.f16.f32 "
        "{%0,%1,%2,%3}, {%4,%5,%6,%7}, {%8,%9}, {%0,%1,%2,%3};"
        : "+f"(d[0]), "+f"(d[1]), "+f"(d[2]), "+f"(d[3])
        : "r"(a[0]), "r"(a[1]), "r"(a[2]), "r"(a[3]), "r"(b[0]), "r"(b[1]));
}
__device__ __forceinline__ void ldsm4(uint32_t* r, uint32_t addr) {
    asm volatile("ldmatrix.sync.aligned.m8n8.x4.shared.b16 {%0,%1,%2,%3}, [%4];"
        : "=r"(r[0]), "=r"(r[1]), "=r"(r[2]), "=r"(r[3]) : "r"(addr));
}
__device__ __forceinline__ void ldsm4t(uint32_t* r, uint32_t addr) {
    asm volatile("ldmatrix.sync.aligned.m8n8.x4.trans.shared.b16 {%0,%1,%2,%3}, [%4];"
        : "=r"(r[0]), "=r"(r[1]), "=r"(r[2]), "=r"(r[3]) : "r"(addr));
}
__device__ __forceinline__ void cp16(uint32_t dst, const void* src) {
    asm volatile("cp.async.cg.shared.global [%0], [%1], 16;" :: "r"(dst), "l"(src));
}

// ============================================================================
// x: fp32 -> fp16 (8 elems / thread, 16B stores)
// ============================================================================
__global__ void conv_x(const float* __restrict__ in, __half* __restrict__ out, int n8)
{
    int i = blockIdx.x * blockDim.x + threadIdx.x;
    if (i < n8) {
        float4 a = ((const float4*)in)[2 * i];
        float4 b = ((const float4*)in)[2 * i + 1];
        half2 h0 = __floats2half2_rn(a.x, a.y), h1 = __floats2half2_rn(a.z, a.w);
        half2 h2 = __floats2half2_rn(b.x, b.y), h3 = __floats2half2_rn(b.z, b.w);
        uint4 r;
        r.x = *(uint32_t*)&h0; r.y = *(uint32_t*)&h1;
        r.z = *(uint32_t*)&h2; r.w = *(uint32_t*)&h3;
        ((uint4*)out)[i] = r;
    }
}

// ============================================================================
// fp16 mma.sync GEMM, W read directly as [K][N] fp16? -> NO: W is fp32 in gmem.
// W tiles are loaded fp32->fp16 by a tiny staging conversion? We instead keep
// W in fp32 and convert during cp? cp.async can't convert. So W halves are
// produced by conv_w below (straight copy, no transpose) once.
// ============================================================================
__global__ void conv_w(const float* __restrict__ in, __half* __restrict__ out, int n8)
{
    int i = blockIdx.x * blockDim.x + threadIdx.x;
    if (i < n8) {
        float4 a = ((const float4*)in)[2 * i];
        float4 b = ((const float4*)in)[2 * i + 1];
        half2 h0 = __floats2half2_rn(a.x, a.y), h1 = __floats2half2_rn(a.z, a.w);
        half2 h2 = __floats2half2_rn(b.x, b.y), h3 = __floats2half2_rn(b.z, b.w);
        uint4 r;
        r.x = *(uint32_t*)&h0; r.y = *(uint32_t*)&h1;
        r.z = *(uint32_t*)&h2; r.w = *(uint32_t*)&h3;
        ((uint4*)out)[i] = r;
    }
}
__device__ __half g_wqh[(size_t)DIMM * DIMM];    // Wq  [K][N] half
__device__ __half g_wkvh[(size_t)DIMM * KVC];    // Wkv [K][N] half
__device__ __half g_woh[(size_t)DIMM * DIMM];    // Wo  [K][N] half

// ============================================================================
// fp16 mma.sync GEMM, B = W[K][N] via ldmatrix.trans (no pre-transpose).
// 128 threads (4 warps, 2M x 2N), CTA 128x128, warp 64x64, BK=64.
// mode 0: fp32 out (O-proj), grid.x = 16 over Wo.
// mode 1: combined projections, grid.x = 24: blocks 0-15 -> Q (rope->qh),
//         blocks 16-23 -> KV (K rope->kh, V transposed scatter->vt).
// smem halves: A0@0, A1@9216, B0@18432, B1@27136  (71680 B total)
// ============================================================================
#define G_SMEM 71680

__global__ __launch_bounds__(128) void gemm_h(
    const __half* __restrict__ A,
    const __half* __restrict__ W0, const __half* __restrict__ W1,
    float* __restrict__ Cf, __half* __restrict__ qh,
    __half* __restrict__ kh, __half* __restrict__ vt,
    const float* __restrict__ cb, const float* __restrict__ sb,
    int M, int K, int mode)
{
    extern __shared__ __half hsm[];
    const uint32_t sbase = smem_u32(hsm);
    const int tid = threadIdx.x;
    const int wid = tid >> 5, lane = tid & 31;
    const int g = lane >> 2, tg = lane & 3;
    const int wm = wid & 1, wn = wid >> 1;
    const int nb = blockIdx.x;
    const int m0 = blockIdx.y * 128;

    const __half* W; int Nw, ncol0;
    if (mode == 0 || nb < 16) { W = W0; Nw = DIMM; ncol0 = nb * 128; }
    else                      { W = W1; Nw = KVC;  ncol0 = (nb - 16) * 128; }

    // A-fragment (non-trans) lane components
    const int arow  = (lane & 7) + ((lane >> 3) & 1) * 8;
    const int akoff = (lane >> 4) * 8;
    // B-fragment (trans from [K][N]) lane components
    const int trow = (lane & 7) + ((lane >> 3) & 1) * 8;   // k offset
    const int tcol = ((lane >> 4) & 1) * 8;                // n offset

    const __half* Ab = A + (size_t)m0 * K;

    float acc[4][8][4];
    #pragma unroll
    for (int mt = 0; mt < 4; ++mt)
        #pragma unroll
        for (int nt = 0; nt < 8; ++nt)
            #pragma unroll
            for (int v = 0; v < 4; ++v) acc[mt][nt][v] = 0.f;

    const int NC = K / 64;

    auto issue_chunk = [&](int s, int k0) {
        const uint32_t abase = sbase + (uint32_t)(s * 9216) * 2u;
        const uint32_t bbase = sbase + (uint32_t)(18432 + s * 8704) * 2u;
        #pragma unroll
        for (int i = 0; i < 8; ++i) {
            const int idx = tid + 128 * i;
            {   // A: [128 m][64 k], pitch 72 halves (144 B)
                const int row = idx >> 3, seg = idx & 7;
                cp16(abase + (uint32_t)(row * 144 + seg * 16),
                     Ab + (size_t)row * K + k0 + seg * 8);
            }
            {   // B: [64 k][128 n], pitch 136 halves (272 B)
                const int row = idx >> 4, seg = idx & 15;
                cp16(bbase + (uint32_t)(row * 272 + seg * 16),
                     W + (size_t)(k0 + row) * Nw + ncol0 + seg * 8);
            }
        }
        asm volatile("cp.async.commit_group;" ::: "memory");
    };

    issue_chunk(0, 0);

    for (int c = 0; c < NC; ++c) {
        const int s = c & 1;
        if (c + 1 < NC) {
            issue_chunk(s ^ 1, (c + 1) * 64);
            asm volatile("cp.async.wait_group 1;" ::: "memory");
        } else {
            asm volatile("cp.async.wait_group 0;" ::: "memory");
        }
        __syncthreads();

        const uint32_t As = sbase + (uint32_t)(s * 9216) * 2u;
        const uint32_t Bs = sbase + (uint32_t)(18432 + s * 8704) * 2u;
        #pragma unroll
        for (int ks = 0; ks < 4; ++ks) {
            uint32_t af[4][4];
            #pragma unroll
            for (int mt = 0; mt < 4; ++mt)
                ldsm4(af[mt], As + (uint32_t)((wm * 64 + mt * 16 + arow) * 72 + ks * 16 + akoff) * 2u);
            #pragma unroll
            for (int ntp = 0; ntp < 4; ++ntp) {
                uint32_t t4[4];
                ldsm4t(t4, Bs + (uint32_t)((ks * 16 + trow) * 136 + wn * 64 + ntp * 16 + tcol) * 2u);
                #pragma unroll
                for (int mt = 0; mt < 4; ++mt) {
                    mma_f16(acc[mt][2 * ntp],     af[mt], t4);
                    mma_f16(acc[mt][2 * ntp + 1], af[mt], t4 + 2);
                }
            }
        }
        __syncthreads();
    }

    // ---- epilogues ----
    if (mode == 0) {
        #pragma unroll
        for (int mt = 0; mt < 4; ++mt) {
            const int row = m0 + wm * 64 + mt * 16 + g;
            #pragma unroll
            for (int nt = 0; nt < 8; ++nt) {
                const int col = ncol0 + wn * 64 + nt * 8 + 2 * tg;
                *(float2*)(Cf + (size_t)row * DIMM + col) =
                    make_float2(acc[mt][nt][0], acc[mt][nt][1]);
                *(float2*)(Cf + (size_t)(row + 8) * DIMM + col) =
                    make_float2(acc[mt][nt][2], acc[mt][nt][3]);
            }
        }
    } else if (nb < 16) {   // Q: rope -> qh
        #pragma unroll
        for (int mt = 0; mt < 4; ++mt) {
            const int row = m0 + wm * 64 + mt * 16 + g;
            const int n1 = row & (SEQ - 1), n2 = (row + 8) & (SEQ - 1);
            #pragma unroll
            for (int nt = 0; nt < 8; ++nt) {
                const int col = ncol0 + wn * 64 + nt * 8 + 2 * tg;
                const int fi = (col & 63) >> 1;
                float c1 = cb[n1 * 32 + fi], s1 = sb[n1 * 32 + fi];
                float c2 = cb[n2 * 32 + fi], s2 = sb[n2 * 32 + fi];
                *(half2*)(qh + (size_t)row * DIMM + col) = __floats2half2_rn(
                    acc[mt][nt][0] * c1 - acc[mt][nt][1] * s1,
                    acc[mt][nt][0] * s1 + acc[mt][nt][1] * c1);
                *(half2*)(qh + (size_t)(row + 8) * DIMM + col) = __floats2half2_rn(
                    acc[mt][nt][2] * c2 - acc[mt][nt][3] * s2,
                    acc[mt][nt][2] * s2 + acc[mt][nt][3] * c2);
            }
        }
    } else {                // KV: K rope -> kh, V transposed scatter -> vt
        #pragma unroll
        for (int mt = 0; mt < 4; ++mt) {
            const int row = m0 + wm * 64 + mt * 16 + g;
            const int n1 = row & (SEQ - 1), n2 = (row + 8) & (SEQ - 1);
            const int b_ = row >> 11;
            #pragma unroll
            for (int nt = 0; nt < 8; ++nt) {
                const int col = ncol0 + wn * 64 + nt * 8 + 2 * tg;
                if (col < 512) {
                    const int fi = (col & 63) >> 1;
                    float c1 = cb[n1 * 32 + fi], s1 = sb[n1 * 32 + fi];
                    float c2 = cb[n2 * 32 + fi], s2 = sb[n2 * 32 + fi];
                    *(half2*)(kh + (size_t)row * 512 + col) = __floats2half2_rn(
                        acc[mt][nt][0] * c1 - acc[mt][nt][1] * s1,
                        acc[mt][nt][0] * s1 + acc[mt][nt][1] * c1);
                    *(half2*)(kh + (size_t)(row + 8) * 512 + col) = __floats2half2_rn(
                        acc[mt][nt][2] * c2 - acc[mt][nt][3] * s2,
                        acc[mt][nt][2] * s2 + acc[mt][nt][3] * c2);
                } else {
                    const int cm = col - 512;
                    const int kvh = cm >> 6, d = cm & 63;
                    __half* vb = vt + ((size_t)((b_ * NKV + kvh) * HD + d)) * SEQ;
                    vb[n1]       = __float2half_rn(acc[mt][nt][0]);
                    vb[SEQ + n1] = __float2half_rn(acc[mt][nt][1]);
                    vb[n2]       = __float2half_rn(acc[mt][nt][2]);
                    vb[SEQ + n2] = __float2half_rn(acc[mt][nt][3]);
                }
            }
        }
    }
}

// ============================================================================
// fp16 tensor-core causal flash attention, GQA h -> h % 8, 128-wide key tiles.
// smem halves: Ps[128][136]@0, Ks[128][72]@17408, Vs[64][136]@26624 (70656 B)
// ============================================================================
#define FH_SMEM 70656
#define QTB     (SEQ / 128)                     // 16

__global__ __launch_bounds__(256) void flash_h(
    const __half* __restrict__ qh, const __half* __restrict__ kh,
    const __half* __restrict__ vt, __half* __restrict__ oh)
{
    extern __shared__ __half fsh[];
    __half* Ps = fsh;                    // [128][136] (Q staging, then P)
    __half* Ks = fsh + 128 * 136;        // [128][72]  rows = keys
    __half* Vs = Ks + 128 * 72;          // [64][136]  rows = dims (V^T)
    const uint32_t Pu = smem_u32(Ps);
    const uint32_t Ku = smem_u32(Ks);
    const uint32_t Vu = smem_u32(Vs);

    const int qtb = (QTB - 1) - blockIdx.x;   // big tiles first
    const int h = blockIdx.y, b = blockIdx.z;
    const int kvh = h & (NKV - 1);
    const int bk = b * NKV + kvh;
    const int tid = threadIdx.x;
    const int wid = tid >> 5, lane = tid & 31;
    const int g = lane >> 2, tg = lane & 3;
    const int wrow = wid * 16;
    const int q0 = qtb * 128;

    const int arow  = (lane & 7) + ((lane >> 3) & 1) * 8;
    const int akoff = (lane >> 4) * 8;
    const int brow  = (lane & 7) + ((lane >> 4) & 1) * 8;
    const int bkoff = ((lane >> 3) & 1) * 8;

    // ---- stage Q (pitch 136) ----
    #pragma unroll
    for (int i = 0; i < 4; ++i) {
        int idx = tid + i * 256;
        int row = idx >> 3, seg = idx & 7;
        *(uint4*)&Ps[row * 136 + seg * 8] =
            *(const uint4*)&qh[(size_t)(b * SEQ + q0 + row) * DIMM + h * HD + seg * 8];
    }
    __syncthreads();

    uint32_t qf[4][4];
    #pragma unroll
    for (int ks = 0; ks < 4; ++ks)
        ldsm4(qf[ks], Pu + (uint32_t)((wrow + arow) * 136 + ks * 16 + akoff) * 2u);

    float m_g = -1e30f, m_g8 = -1e30f, l_g = 0.f, l_g8 = 0.f;
    float acc[8][4];
    #pragma unroll
    for (int nt = 0; nt < 8; ++nt)
        #pragma unroll
        for (int v = 0; v < 4; ++v) acc[nt][v] = 0.f;

    // prologue: prefetch tile 0 (K: 128x64, V: 64x128)
    uint4 kr[4], vr[4];
    #pragma unroll
    for (int i = 0; i < 4; ++i) {
        int idx = tid + i * 256;
        { int r = idx >> 3, seg = idx & 7;
          kr[i] = *(const uint4*)&kh[(size_t)(b * SEQ + r) * 512 + kvh * HD + seg * 8]; }
        { int r = idx >> 4, seg = idx & 15;
          vr[i] = *(const uint4*)&vt[((size_t)bk * HD + r) * SEQ + seg * 8]; }
    }

    for (int kt = 0; kt <= qtb; ++kt) {
        __syncthreads();
        #pragma unroll
        for (int i = 0; i < 4; ++i) {
            int idx = tid + i * 256;
            { int r = idx >> 3, seg = idx & 7;
              *(uint4*)&Ks[r * 72 + seg * 8] = kr[i]; }
            { int r = idx >> 4, seg = idx & 15;
              *(uint4*)&Vs[r * 136 + seg * 8] = vr[i]; }
        }
        __syncthreads();

        if (kt < qtb) {
            #pragma unroll
            for (int i = 0; i < 4; ++i) {
                int idx = tid + i * 256;
                { int r = idx >> 3, seg = idx & 7;
                  kr[i] = *(const uint4*)&kh[(size_t)(b * SEQ + (kt + 1) * 128 + r) * 512 + kvh * HD + seg * 8]; }
                { int r = idx >> 4, seg = idx & 15;
                  vr[i] = *(const uint4*)&vt[((size_t)bk * HD + r) * SEQ + (kt + 1) * 128 + seg * 8]; }
            }
        }

        // ---- S = Q @ K^T  (128 keys) ----
        float sA[16][4];
        #pragma unroll
        for (int nt = 0; nt < 16; ++nt)
            #pragma unroll
            for (int v = 0; v < 4; ++v) sA[nt][v] = 0.f;
        #pragma unroll
        for (int ks = 0; ks < 4; ++ks) {
            #pragma unroll
            for (int ntp = 0; ntp < 8; ++ntp) {
                uint32_t t4[4];
                ldsm4(t4, Ku + (uint32_t)((ntp * 16 + brow) * 72 + ks * 16 + bkoff) * 2u);
                mma_f16(sA[2 * ntp],     qf[ks], t4);
                mma_f16(sA[2 * ntp + 1], qf[ks], t4 + 2);
            }
        }
        #pragma unroll
        for (int nt = 0; nt < 16; ++nt) {
            sA[nt][0] *= 0.125f; sA[nt][1] *= 0.125f;
            sA[nt][2] *= 0.125f; sA[nt][3] *= 0.125f;
        }

        // ---- causal mask (diagonal tile only) ----
        if (kt == qtb) {
            const int r1 = wrow + g, r2 = wrow + g + 8;
            #pragma unroll
            for (int nt = 0; nt < 16; ++nt) {
                const int col = nt * 8 + 2 * tg;
                if (col > r1)     sA[nt][0] = -1e30f;
                if (col + 1 > r1) sA[nt][1] = -1e30f;
                if (col > r2)     sA[nt][2] = -1e30f;
                if (col + 1 > r2) sA[nt][3] = -1e30f;
            }
        }

        // ---- online softmax ----
        float mxg = -1e30f, mxg8 = -1e30f;
        #pragma unroll
        for (int nt = 0; nt < 16; ++nt) {
            mxg  = fmaxf(mxg,  fmaxf(sA[nt][0], sA[nt][1]));
            mxg8 = fmaxf(mxg8, fmaxf(sA[nt][2], sA[nt][3]));
        }
        mxg  = fmaxf(mxg,  __shfl_xor_sync(0xffffffffu, mxg, 1));
        mxg  = fmaxf(mxg,  __shfl_xor_sync(0xffffffffu, mxg, 2));
        mxg8 = fmaxf(mxg8, __shfl_xor_sync(0xffffffffu, mxg8, 1));
        mxg8 = fmaxf(mxg8, __shfl_xor_sync(0xffffffffu, mxg8, 2));

        const float mn_g  = fmaxf(m_g,  mxg);
        const float mn_g8 = fmaxf(m_g8, mxg8);
        const float cr_g  = __expf(m_g  - mn_g);
        const float cr_g8 = __expf(m_g8 - mn_g8);

        float sum_g = 0.f, sum_g8 = 0.f;
        #pragma unroll
        for (int nt = 0; nt < 16; ++nt) {
            sA[nt][0] = __expf(sA[nt][0] - mn_g);
            sA[nt][1] = __expf(sA[nt][1] - mn_g);
            sA[nt][2] = __expf(sA[nt][2] - mn_g8);
            sA[nt][3] = __expf(sA[nt][3] - mn_g8);
            sum_g  += sA[nt][0] + sA[nt][1];
            sum_g8 += sA[nt][2] + sA[nt][3];
        }
        sum_g  += __shfl_xor_sync(0xffffffffu, sum_g, 1);
        sum_g  += __shfl_xor_sync(0xffffffffu, sum_g, 2);
        sum_g8 += __shfl_xor_sync(0xffffffffu, sum_g8, 1);
        sum_g8 += __shfl_xor_sync(0xffffffffu, sum_g8, 2);

        m_g = mn_g;  l_g  = l_g  * cr_g  + sum_g;
        m_g8 = mn_g8; l_g8 = l_g8 * cr_g8 + sum_g8;

        // ---- P -> smem (per-warp-private rows, pitch 136) ----
        {
            __half* pr = Ps + (wrow + g) * 136;
            #pragma unroll
            for (int nt = 0; nt < 16; ++nt) {
                *(half2*)(pr + nt * 8 + 2 * tg) = __floats2half2_rn(sA[nt][0], sA[nt][1]);
                *(half2*)(pr + 8 * 136 + nt * 8 + 2 * tg) = __floats2half2_rn(sA[nt][2], sA[nt][3]);
            }
        }
        __syncwarp();

        #pragma unroll
        for (int nt = 0; nt < 8; ++nt) {
            acc[nt][0] *= cr_g;  acc[nt][1] *= cr_g;
            acc[nt][2] *= cr_g8; acc[nt][3] *= cr_g8;
        }

        // ---- O += P @ V  (k = 128 keys -> 8 ks steps) ----
        #pragma unroll
        for (int ks = 0; ks < 8; ++ks) {
            uint32_t af[4];
            ldsm4(af, Pu + (uint32_t)((wrow + arow) * 136 + ks * 16 + akoff) * 2u);
            #pragma unroll
            for (int ntp = 0; ntp < 4; ++ntp) {
                uint32_t t4[4];
                ldsm4(t4, Vu + (uint32_t)((ntp * 16 + brow) * 136 + ks * 16 + bkoff) * 2u);
                mma_f16(acc[2 * ntp],     af, t4);
                mma_f16(acc[2 * ntp + 1], af, t4 + 2);
            }
        }
    }

    // ---- epilogue ----
    const float il_g = 1.f / l_g, il_g8 = 1.f / l_g8;
    __half* ob  = oh + (size_t)(b * SEQ + q0 + wrow + g) * DIMM + h * HD;
    __half* ob8 = ob + 8 * DIMM;
    #pragma unroll
    for (int nt = 0; nt < 8; ++nt) {
        const int col = nt * 8 + 2 * tg;
        *(half2*)(ob + col)  = __floats2half2_rn(acc[nt][0] * il_g,  acc[nt][1] * il_g);
        *(half2*)(ob8 + col) = __floats2half2_rn(acc[nt][2] * il_g8, acc[nt][3] * il_g8);
    }
}

// ============================================================================
extern "C" void kernel_launch(void* const* d_in, const int* in_sizes, int n_in,
                              void* d_out, int out_size)
{
    const float* x   = (const float*)d_in[0];
    const float* Wq  = (const float*)d_in[1];
    const float* Wkv = (const float*)d_in[2];
    const float* Wo  = (const float*)d_in[3];
    const float* cb  = (const float*)d_in[4];
    const float* sb  = (const float*)d_in[5];
    float* out = (float*)d_out;

    __half *xh, *qhp, *khp, *vtp, *ahp, *wqh, *wkvh, *woh;
    cudaGetSymbolAddress((void**)&xh,   g_xh);
    cudaGetSymbolAddress((void**)&qhp,  g_qh);
    cudaGetSymbolAddress((void**)&khp,  g_kh);
    cudaGetSymbolAddress((void**)&vtp,  g_vt);
    cudaGetSymbolAddress((void**)&ahp,  g_ah);
    cudaGetSymbolAddress((void**)&wqh,  g_wqh);
    cudaGetSymbolAddress((void**)&wkvh, g_wkvh);
    cudaGetSymbolAddress((void**)&woh,  g_woh);

    cudaFuncSetAttribute(gemm_h,
                         cudaFuncAttributeMaxDynamicSharedMemorySize, G_SMEM);
    cudaFuncSetAttribute(flash_h,
                         cudaFuncAttributeMaxDynamicSharedMemorySize, FH_SMEM);

    // convert x and weights to fp16 (no transpose; gemm uses ldmatrix.trans)
    {
        int n8 = NTOK * DIMM / 8;
        conv_x<<<(n8 + 255) / 256, 256>>>(x, xh, n8);
        int w8 = DIMM * DIMM / 8;
        conv_w<<<(w8 + 255) / 256, 256>>>(Wq, wqh, w8);
        conv_w<<<(w8 + 255) / 256, 256>>>(Wo, woh, w8);
        int kv8 = DIMM * KVC / 8;
        conv_w<<<(kv8 + 255) / 256, 256>>>(Wkv, wkvh, kv8);
    }

    // combined Q+KV projection (fused rope / V-transpose epilogues)
    gemm_h<<<dim3(24, NTOK / 128), 128, G_SMEM>>>(
        xh, wqh, wkvh, nullptr, qhp, khp, vtp, cb, sb, NTOK, DIMM, 1);

    // fp16 tensor-core causal GQA flash attention (128-wide key tiles)
    flash_h<<<dim3(QTB, NH, BATCH), 256, FH_SMEM>>>(qhp, khp, vtp, ahp);

    // out = att @ Wo (fp32 out)
    gemm_h<<<dim3(16, NTOK / 128), 128, G_SMEM>>>(
        ahp, woh, nullptr, out, nullptr, nullptr, nullptr, nullptr, nullptr,
        NTOK, DIMM, 0);
}